// round 14
// baseline (speedup 1.0000x reference)
#include <cuda_runtime.h>
#include <cuda_bf16.h>
#include <cuda_fp16.h>

#define SEQ    6272
#define NKT    98      // total key tiles of 64
#define KCH    3       // key chunks (split-K)
#define LOG2E  1.44269504f

// ---------------- device scratch (allocation-free) ----------------
__device__ __align__(256) __nv_bfloat16 g_xh[2*256*SEQ], g_xl[2*256*SEQ];   // x split, (n,c,l)
__device__ __align__(256) __nv_bfloat16 g_wsh[3*128*256], g_wsl[3*128*256]; // g,theta,phi weights
__device__ __align__(256) __half       g_wzf[256*128];                       // wz single fp16
__device__ __align__(256) __nv_bfloat16 g_qh[2*SEQ*128], g_ql[2*SEQ*128];   // theta, (n,l,h)
__device__ __align__(256) __nv_bfloat16 g_kh[2*SEQ*128], g_kl[2*SEQ*128];   // phi * log2e, (n,l,h)
__device__ __align__(256) __half       g_vf[2*128*SEQ];                      // g, fp16, (n,h,l)
__device__ __align__(256) __half       g_ypart[2*KCH*SEQ*128];               // normalized partial y (fp16)
__device__ __align__(256) float g_zp[2*KCH*SEQ], g_mp[2*KCH*SEQ];            // partial Z, shift m (log2)

__device__ __forceinline__ unsigned smaddr(const void* p) {
    unsigned r;
    asm("{.reg .u64 t; cvta.to.shared.u64 t, %1; cvt.u32.u64 %0, t;}" : "=r"(r) : "l"(p));
    return r;
}
__device__ __forceinline__ void cp16(unsigned s, const void* g) {
    asm volatile("cp.async.cg.shared.global [%0], [%1], 16;" :: "r"(s), "l"(g) : "memory");
}
#define CP_COMMIT()  asm volatile("cp.async.commit_group;" ::: "memory")
#define CP_WAIT(N)   asm volatile("cp.async.wait_group %0;" :: "n"(N) : "memory")

__device__ __forceinline__ void ldsm4(unsigned* r, unsigned a) {
    asm volatile("ldmatrix.sync.aligned.m8n8.x4.shared.b16 {%0,%1,%2,%3}, [%4];"
        : "=r"(r[0]), "=r"(r[1]), "=r"(r[2]), "=r"(r[3]) : "r"(a));
}
__device__ __forceinline__ void ldsm4t(unsigned* r, unsigned a) {
    asm volatile("ldmatrix.sync.aligned.m8n8.x4.trans.shared.b16 {%0,%1,%2,%3}, [%4];"
        : "=r"(r[0]), "=r"(r[1]), "=r"(r[2]), "=r"(r[3]) : "r"(a));
}
__device__ __forceinline__ void mma_bf16(float* c, const unsigned* a, const unsigned* b) {
    asm volatile("mma.sync.aligned.m16n8k16.row.col.f32.bf16.bf16.f32 "
        "{%0,%1,%2,%3}, {%4,%5,%6,%7}, {%8,%9}, {%0,%1,%2,%3};"
        : "+f"(c[0]), "+f"(c[1]), "+f"(c[2]), "+f"(c[3])
        : "r"(a[0]), "r"(a[1]), "r"(a[2]), "r"(a[3]), "r"(b[0]), "r"(b[1]));
}
__device__ __forceinline__ void mma_f16(float* c, const unsigned* a, const unsigned* b) {
    asm volatile("mma.sync.aligned.m16n8k16.row.col.f32.f16.f16.f32 "
        "{%0,%1,%2,%3}, {%4,%5,%6,%7}, {%8,%9}, {%0,%1,%2,%3};"
        : "+f"(c[0]), "+f"(c[1]), "+f"(c[2]), "+f"(c[3])
        : "r"(a[0]), "r"(a[1]), "r"(a[2]), "r"(a[3]), "r"(b[0]), "r"(b[1]));
}
__device__ __forceinline__ void splitpack(float a, float b, unsigned &h, unsigned &l) {
    __nv_bfloat16 ha = __float2bfloat16(a), hb = __float2bfloat16(b);
    float la = a - __bfloat162float(ha), lb = b - __bfloat162float(hb);
    __nv_bfloat16 lA = __float2bfloat16(la), lB = __float2bfloat16(lb);
    h = (unsigned)__bfloat16_as_ushort(ha) | ((unsigned)__bfloat16_as_ushort(hb) << 16);
    l = (unsigned)__bfloat16_as_ushort(lA) | ((unsigned)__bfloat16_as_ushort(lB) << 16);
}
__device__ __forceinline__ unsigned packh2(float lo, float hi) {
    unsigned u;
    asm("cvt.rn.f16x2.f32 %0, %1, %2;" : "=r"(u) : "f"(hi), "f"(lo));
    return u;
}
__device__ __forceinline__ float ex2(float x) {
    float r;
    asm("ex2.approx.ftz.f32 %0, %1;" : "=f"(r) : "f"(x));
    return r;
}

// ---------------------------------------------------------------------------
// Kernel 0: split x + g/theta/phi weights into bf16 hi/lo; wz into fp16.
// ---------------------------------------------------------------------------
__global__ void __launch_bounds__(256) split_kernel(
    const float* __restrict__ x,
    const float* __restrict__ gw, const float* __restrict__ tw,
    const float* __restrict__ pw, const float* __restrict__ zw)
{
    const int bid = blockIdx.x, tid = threadIdx.x;
    if (bid < 3136) {
        int i = bid * 256 + tid;
        float4 v = ((const float4*)x)[i];
        unsigned h0, l0, h1, l1;
        splitpack(v.x, v.y, h0, l0);
        splitpack(v.z, v.w, h1, l1);
        *(uint2*)(g_xh + 4*(size_t)i) = make_uint2(h0, h1);
        *(uint2*)(g_xl + 4*(size_t)i) = make_uint2(l0, l1);
    } else {
        int j = (bid - 3136) * 256 + tid;
        int lj = j & 8191;
        if (j < 24576) {
            const float* src;
            __nv_bfloat16 *dh, *dl;
            if (j < 8192)       { src = gw; dh = g_wsh;           dl = g_wsl; }
            else if (j < 16384) { src = tw; dh = g_wsh + 32768;   dl = g_wsl + 32768; }
            else                { src = pw; dh = g_wsh + 65536;   dl = g_wsl + 65536; }
            float4 v = ((const float4*)src)[lj];
            unsigned h0, l0, h1, l1;
            splitpack(v.x, v.y, h0, l0);
            splitpack(v.z, v.w, h1, l1);
            *(uint2*)(dh + 4*lj) = make_uint2(h0, h1);
            *(uint2*)(dl + 4*lj) = make_uint2(l0, l1);
        } else {
            float4 v = ((const float4*)zw)[lj];
            *(uint2*)(g_wzf + 4*lj) = make_uint2(packh2(v.x, v.y), packh2(v.z, v.w));
        }
    }
}

// ---------------------------------------------------------------------------
// Kernel 1: projections on HMMA (3-pass bf16). Q out: bf16 hi/lo.
// K (pidx 2) out: bf16 hi/lo of (phi * log2e). V (pidx 0) out: fp16, (n,h,l).
// ---------------------------------------------------------------------------
#define PJ_XP 272
#define PJ_WP 144
#define SM_PX 0
#define SM_PW 69632
#define EP_P  272
#define PROJ_SMEM 143360

__global__ void __launch_bounds__(256, 1) proj_tc(
    const float* __restrict__ gb, const float* __restrict__ tb,
    const float* __restrict__ pb)
{
    extern __shared__ char smc[];
    const unsigned smb = smaddr(smc);
    const int tid = threadIdx.x, wid = tid >> 5, lane = tid & 31;
    const int g = lane >> 2, t = lane & 3, r8 = lane & 7, quad = lane >> 3;
    const int pidx = blockIdx.y, nn = blockIdx.z;
    const int L0 = blockIdx.x * 128;
    const int rw = wid * 16;

    const float* bias = (pidx == 0) ? gb : (pidx == 1) ? tb : pb;
    const __nv_bfloat16* Xh = g_xh + (size_t)nn * 256 * SEQ;
    const __nv_bfloat16* Xl = g_xl + (size_t)nn * 256 * SEQ;
    const __nv_bfloat16* Wh = g_wsh + pidx * 32768;
    const __nv_bfloat16* Wl = g_wsl + pidx * 32768;

    auto load_chunk = [&](int ck, int buf) {
        const unsigned xb = smb + SM_PX + buf * 34816;
        const unsigned wb = smb + SM_PW + buf * 36864;
        #pragma unroll
        for (int k = 0; k < 8; k++) {
            int c = tid + 256 * k;
            int half = c >> 10, cc = c & 1023;
            int row = cc >> 4, col8 = cc & 15;
            cp16(xb + half * 17408 + row * PJ_XP + col8 * 16,
                 (half ? Xl : Xh) + ((size_t)(ck * 64 + row)) * SEQ + L0 + col8 * 8);
        }
        #pragma unroll
        for (int k = 0; k < 8; k++) {
            int c = tid + 256 * k;
            int half = c >> 10, cc = c & 1023;
            int row = cc >> 3, col8 = cc & 7;
            cp16(wb + half * 18432 + row * PJ_WP + col8 * 16,
                 (half ? Wl : Wh) + (size_t)row * 256 + ck * 64 + col8 * 8);
        }
        CP_COMMIT();
    };

    load_chunk(0, 0);

    float s[16][4];
    #pragma unroll
    for (int i = 0; i < 16; i++)
        #pragma unroll
        for (int j = 0; j < 4; j++) s[i][j] = 0.f;

    const unsigned xt_rowA = (unsigned)((quad >> 1) * 8 + r8);
    const unsigned xt_colA = (unsigned)(rw + (quad & 1) * 8) * 2;
    const unsigned xt_rowB = (unsigned)((quad & 1) * 8 + r8);
    const unsigned wB_row = (unsigned)(r8 + (quad >> 1) * 8);
    const unsigned wB_col = (unsigned)((quad & 1) * 16);
    const unsigned wA_off0 = (unsigned)(rw + r8 + (quad & 1) * 8) * PJ_WP + (unsigned)((quad >> 1) * 16);

    for (int ck = 0; ck < 4; ck++) {
        const int b = ck & 1;
        if (ck + 1 < 4) { load_chunk(ck + 1, b ^ 1); CP_WAIT(1); }
        else            { CP_WAIT(0); }
        __syncthreads();

        const unsigned xh = smb + SM_PX + b * 34816, xl = xh + 17408;
        const unsigned wh = smb + SM_PW + b * 36864, wl = wh + 18432;

        if (pidx != 0) {
            #pragma unroll
            for (int kk = 0; kk < 4; kk++) {
                unsigned Ah[4], Al[4];
                unsigned aoff = (kk * 16 + xt_rowA) * PJ_XP + xt_colA;
                ldsm4t(Ah, xh + aoff);
                ldsm4t(Al, xl + aoff);
                #pragma unroll
                for (int nb = 0; nb < 8; nb++) {
                    unsigned Bh[4], Bl[4];
                    unsigned boff = (nb * 16 + wB_row) * PJ_WP + kk * 32 + wB_col;
                    ldsm4(Bh, wh + boff);
                    ldsm4(Bl, wl + boff);
                    mma_bf16(s[2*nb],   Ah, Bh);  mma_bf16(s[2*nb+1], Ah, Bh + 2);
                    mma_bf16(s[2*nb],   Ah, Bl);  mma_bf16(s[2*nb+1], Ah, Bl + 2);
                    mma_bf16(s[2*nb],   Al, Bh);  mma_bf16(s[2*nb+1], Al, Bh + 2);
                }
            }
        } else {
            #pragma unroll
            for (int kk = 0; kk < 4; kk++) {
                unsigned Ah[4], Al[4];
                unsigned aoff = wA_off0 + kk * 32;
                ldsm4(Ah, wh + aoff);
                ldsm4(Al, wl + aoff);
                #pragma unroll
                for (int nb = 0; nb < 8; nb++) {
                    unsigned Bh[4], Bl[4];
                    unsigned boff = (kk * 16 + xt_rowB) * PJ_XP + (nb * 16 + (quad >> 1) * 8) * 2;
                    ldsm4t(Bh, xh + boff);
                    ldsm4t(Bl, xl + boff);
                    mma_bf16(s[2*nb],   Ah, Bh);  mma_bf16(s[2*nb+1], Ah, Bh + 2);
                    mma_bf16(s[2*nb],   Ah, Bl);  mma_bf16(s[2*nb+1], Ah, Bl + 2);
                    mma_bf16(s[2*nb],   Al, Bh);  mma_bf16(s[2*nb+1], Al, Bh + 2);
                }
            }
        }
        __syncthreads();
    }

    if (pidx != 0) {
        // Q (pidx 1) plain; K (pidx 2) scaled by log2e so softmax uses ex2.
        const float sc = (pidx == 2) ? LOG2E : 1.0f;
        #pragma unroll
        for (int j = 0; j < 16; j++) {
            int h = 8 * j + 2 * t;
            float b0 = __ldg(bias + h), b1 = __ldg(bias + h + 1);
            unsigned hw, lw;
            splitpack((s[j][0] + b0) * sc, (s[j][1] + b1) * sc, hw, lw);
            *(unsigned*)(smc + (rw + g) * EP_P + h * 2)           = hw;
            *(unsigned*)(smc + 34816 + (rw + g) * EP_P + h * 2)   = lw;
            splitpack((s[j][2] + b0) * sc, (s[j][3] + b1) * sc, hw, lw);
            *(unsigned*)(smc + (rw + g + 8) * EP_P + h * 2)         = hw;
            *(unsigned*)(smc + 34816 + (rw + g + 8) * EP_P + h * 2) = lw;
        }
        __syncthreads();
        __nv_bfloat16* Dh = (pidx == 1) ? g_qh : g_kh;
        __nv_bfloat16* Dl = (pidx == 1) ? g_ql : g_kl;
        #pragma unroll
        for (int k = 0; k < 8; k++) {
            int idx = tid + 256 * k;
            int row = idx >> 4, c16 = idx & 15;
            size_t go = ((size_t)nn * SEQ + L0 + row) * 128 + c16 * 8;
            *(uint4*)(Dh + go) = *(const uint4*)(smc + row * EP_P + c16 * 16);
            *(uint4*)(Dl + go) = *(const uint4*)(smc + 34816 + row * EP_P + c16 * 16);
        }
    } else {
        // V: single fp16, rows = h, cols = l
        const int h0 = rw + g;
        float br0 = __ldg(bias + h0), br1 = __ldg(bias + h0 + 8);
        #pragma unroll
        for (int j = 0; j < 16; j++) {
            int l = 8 * j + 2 * t;
            *(unsigned*)(smc + h0 * EP_P + l * 2)       = packh2(s[j][0] + br0, s[j][1] + br0);
            *(unsigned*)(smc + (h0 + 8) * EP_P + l * 2) = packh2(s[j][2] + br1, s[j][3] + br1);
        }
        __syncthreads();
        #pragma unroll
        for (int k = 0; k < 8; k++) {
            int idx = tid + 256 * k;
            int row = idx >> 4, c16 = idx & 15;
            size_t go = ((size_t)nn * 128 + row) * SEQ + L0 + c16 * 8;
            *(uint4*)(g_vf + go) = *(const uint4*)(smc + row * EP_P + c16 * 16);
        }
    }
}

// ---------------------------------------------------------------------------
// Kernel 2: flash attention — QK 3-pass bf16 (log2-domain), PV fp16,
// online softmax SUB-TILED into two 32-key halves so MUFU/ALU of one half
// overlaps HMMA of the other. Vote-skipped O rescale. ex2 throughout.
// ---------------------------------------------------------------------------
#define QSTR 272
#define VSTR 144
#define SM_QH 0
#define SM_QL 34816
#define SM_K  69632        // 2 bufs x (hi 17408 + lo 17408)
#define SM_V  139264       // 2 bufs x 18432 (fp16 single)
#define ATTN_SMEM 176128

__device__ __forceinline__ void load_kv(
    unsigned smb, int jt, int buf, int tid,
    const __nv_bfloat16* Kh, const __nv_bfloat16* Kl,
    const __half* Vf)
{
    const unsigned kb = smb + SM_K + buf * 34816;
    const unsigned vb = smb + SM_V + buf * 18432;
    #pragma unroll
    for (int k = 0; k < 8; k++) {                 // K: 64 rows x 128ch, hi+lo
        int c = tid + 256 * k;
        int half = c >> 10, cc = c & 1023;
        int row = cc >> 4, col16 = cc & 15;
        cp16(kb + half * 17408 + row * QSTR + col16 * 16,
             (half ? Kl : Kh) + ((size_t)(jt * 64 + row)) * 128 + col16 * 8);
    }
    #pragma unroll
    for (int k = 0; k < 4; k++) {                 // V^T fp16: 128 rows(ch) x 64 keys
        int c = tid + 256 * k;
        int row = c >> 3, col = c & 7;
        cp16(vb + row * VSTR + col * 16,
             Vf + (size_t)row * SEQ + jt * 64 + col * 8);
    }
}

__global__ void __launch_bounds__(256, 1) attn_kernel()
{
    extern __shared__ char smc[];
    const unsigned smb = smaddr(smc);
    const int tid = threadIdx.x, wid = tid >> 5, lane = tid & 31;
    const int g = lane >> 2, t = lane & 3, r8 = lane & 7, quad = lane >> 3;
    const int kc = blockIdx.y, n = blockIdx.z, q0 = blockIdx.x * 128;
    const int start = kc * 33;
    const int cnt = (kc == KCH - 1) ? (NKT - 33 * (KCH - 1)) : 33;
    const int rw = wid * 16;

    const __nv_bfloat16* Qh = g_qh + (size_t)n * SEQ * 128;
    const __nv_bfloat16* Ql = g_ql + (size_t)n * SEQ * 128;
    const __nv_bfloat16* Kh = g_kh + (size_t)n * SEQ * 128;
    const __nv_bfloat16* Kl = g_kl + (size_t)n * SEQ * 128;
    const __half*        Vf = g_vf + (size_t)n * 128 * SEQ;

    const unsigned qa_off = (unsigned)(rw + r8 + (quad & 1) * 8) * QSTR + (unsigned)(quad >> 1) * 16;
    const unsigned kb_off = (unsigned)(r8 + (quad >> 1) * 8) * QSTR + (unsigned)(quad & 1) * 16;
    const unsigned vb_off = (unsigned)(r8 + (quad >> 1) * 8) * VSTR + (unsigned)(quad & 1) * 16;

    #pragma unroll
    for (int k = 0; k < 16; k++) {
        int c = tid + 256 * k;
        int half = c >> 11, cc = c & 2047;
        int row = cc >> 4, col16 = cc & 15;
        cp16(smb + (half ? SM_QL : SM_QH) + row * QSTR + col16 * 16,
             (half ? Ql : Qh) + ((size_t)(q0 + row)) * 128 + col16 * 8);
    }
    load_kv(smb, start, 0, tid, Kh, Kl, Vf);
    CP_COMMIT();

    float o[16][4];
    #pragma unroll
    for (int i = 0; i < 16; i++)
        #pragma unroll
        for (int j = 0; j < 4; j++) o[i][j] = 0.f;
    float z0 = 0.f, z1 = 0.f, m0 = -1e30f, m1 = -1e30f;

    // softmax + PV for one 32-key sub-tile (cols kkb*16 .. kkb*16+31)
    auto process_sub = [&](float (&sv)[4][4], int kkb, unsigned vbf) {
        float a0 = -1e30f, a1 = -1e30f;
        #pragma unroll
        for (int i = 0; i < 4; i++) {
            a0 = fmaxf(a0, fmaxf(sv[i][0], sv[i][1]));
            a1 = fmaxf(a1, fmaxf(sv[i][2], sv[i][3]));
        }
        a0 = fmaxf(a0, __shfl_xor_sync(0xffffffffu, a0, 1));
        a0 = fmaxf(a0, __shfl_xor_sync(0xffffffffu, a0, 2));
        a1 = fmaxf(a1, __shfl_xor_sync(0xffffffffu, a1, 1));
        a1 = fmaxf(a1, __shfl_xor_sync(0xffffffffu, a1, 2));
        float mn0 = fmaxf(m0, a0), mn1 = fmaxf(m1, a1);
        float al0 = ex2(m0 - mn0), al1 = ex2(m1 - mn1);
        m0 = mn0; m1 = mn1;
        if (!__all_sync(0xffffffffu, (al0 == 1.0f) && (al1 == 1.0f))) {
            z0 *= al0; z1 *= al1;
            #pragma unroll
            for (int ct = 0; ct < 16; ct++) {
                o[ct][0] *= al0; o[ct][1] *= al0;
                o[ct][2] *= al1; o[ct][3] *= al1;
            }
        }
        #pragma unroll
        for (int i = 0; i < 4; i++) {
            float p0 = ex2(sv[i][0] - m0), p1 = ex2(sv[i][1] - m0);
            float p2 = ex2(sv[i][2] - m1), p3 = ex2(sv[i][3] - m1);
            sv[i][0] = p0; sv[i][1] = p1; sv[i][2] = p2; sv[i][3] = p3;
            z0 += p0 + p1; z1 += p2 + p3;
        }
        #pragma unroll
        for (int k2 = 0; k2 < 2; k2++) {
            unsigned Af[4];
            Af[0] = packh2(sv[2*k2][0],   sv[2*k2][1]);
            Af[1] = packh2(sv[2*k2][2],   sv[2*k2][3]);
            Af[2] = packh2(sv[2*k2+1][0], sv[2*k2+1][1]);
            Af[3] = packh2(sv[2*k2+1][2], sv[2*k2+1][3]);
            const int kk = kkb + k2;
            #pragma unroll
            for (int cp = 0; cp < 8; cp++) {
                unsigned Bf[4];
                ldsm4(Bf, vbf + vb_off + (unsigned)cp * (16 * VSTR) + kk * 32);
                mma_f16(o[2*cp],   Af, Bf);
                mma_f16(o[2*cp+1], Af, Bf + 2);
            }
        }
    };

    for (int it = 0; it < cnt; it++) {
        const int b = it & 1;
        if (it + 1 < cnt) {
            load_kv(smb, start + it + 1, b ^ 1, tid, Kh, Kl, Vf);
            CP_COMMIT();
            CP_WAIT(1);
        } else {
            CP_WAIT(0);
        }
        __syncthreads();

        const unsigned kbh = smb + SM_K + b * 34816;
        const unsigned kbl = kbh + 17408;
        const unsigned vbf = smb + SM_V + b * 18432;

        float s0[4][4], s1[4][4];
        #pragma unroll
        for (int i = 0; i < 4; i++)
            #pragma unroll
            for (int j = 0; j < 4; j++) { s0[i][j] = 0.f; s1[i][j] = 0.f; }

        // ---- QK sub0 (cols 0-31) ----
        #pragma unroll
        for (int kk = 0; kk < 8; kk++) {
            unsigned Ah[4], Al[4];
            ldsm4(Ah, smb + SM_QH + qa_off + kk * 32);
            ldsm4(Al, smb + SM_QL + qa_off + kk * 32);
            #pragma unroll
            for (int p = 0; p < 2; p++) {
                unsigned Bh[4], Bl[4];
                unsigned off = kb_off + (unsigned)p * (16 * QSTR) + kk * 32;
                ldsm4(Bh, kbh + off);
                ldsm4(Bl, kbl + off);
                mma_bf16(s0[2*p],   Ah, Bh);   mma_bf16(s0[2*p+1], Ah, Bh + 2);
                mma_bf16(s0[2*p],   Ah, Bl);   mma_bf16(s0[2*p+1], Ah, Bl + 2);
                mma_bf16(s0[2*p],   Al, Bh);   mma_bf16(s0[2*p+1], Al, Bh + 2);
            }
        }
        // ---- QK sub1 (cols 32-63): independent — its HMMAs drain while
        //      softmax(sub0)'s MUFU/ALU below issue on the other pipes ----
        #pragma unroll
        for (int kk = 0; kk < 8; kk++) {
            unsigned Ah[4], Al[4];
            ldsm4(Ah, smb + SM_QH + qa_off + kk * 32);
            ldsm4(Al, smb + SM_QL + qa_off + kk * 32);
            #pragma unroll
            for (int p = 0; p < 2; p++) {
                unsigned Bh[4], Bl[4];
                unsigned off = kb_off + (unsigned)(p + 2) * (16 * QSTR) + kk * 32;
                ldsm4(Bh, kbh + off);
                ldsm4(Bl, kbl + off);
                mma_bf16(s1[2*p],   Ah, Bh);   mma_bf16(s1[2*p+1], Ah, Bh + 2);
                mma_bf16(s1[2*p],   Ah, Bl);   mma_bf16(s1[2*p+1], Ah, Bl + 2);
                mma_bf16(s1[2*p],   Al, Bh);   mma_bf16(s1[2*p+1], Al, Bh + 2);
            }
        }

        process_sub(s0, 0, vbf);   // softmax(sub0) overlaps QK(sub1); PV(sub0)
        process_sub(s1, 2, vbf);   // softmax(sub1) overlaps PV(sub0); PV(sub1)
        __syncthreads();
    }

    z0 += __shfl_xor_sync(0xffffffffu, z0, 1);
    z0 += __shfl_xor_sync(0xffffffffu, z0, 2);
    z1 += __shfl_xor_sync(0xffffffffu, z1, 1);
    z1 += __shfl_xor_sync(0xffffffffu, z1, 2);
    const float i0 = 1.0f / z0, i1 = 1.0f / z1;

    const size_t rbase = ((size_t)(n * KCH + kc)) * SEQ + q0 + rw + g;
    __half* y0 = g_ypart + rbase * 128;
    __half* y1 = y0 + 8 * 128;
    #pragma unroll
    for (int ct = 0; ct < 16; ct++) {
        int col = 8 * ct + 2 * t;
        *(unsigned*)(y0 + col) = packh2(o[ct][0] * i0, o[ct][1] * i0);
        *(unsigned*)(y1 + col) = packh2(o[ct][2] * i1, o[ct][3] * i1);
    }
    if (t == 0) {
        g_zp[rbase]     = z0;  g_mp[rbase]     = m0;
        g_zp[rbase + 8] = z1;  g_mp[rbase + 8] = m1;
    }
}

// ---------------------------------------------------------------------------
// Kernel 3: combine normalized fp16 partials + output projection (fp16 MMA).
// coef_i = 2^(m_i - M) * z_i / Z  (m in log2 domain).
// ---------------------------------------------------------------------------
#define OT_P 272
#define SM_WZF 0
#define SM_YF  34816
#define SM_CF  52224
#define OUT_SMEM 52992

__global__ void __launch_bounds__(256, 2) out_tc(
    const float* __restrict__ x, const float* __restrict__ bz,
    float* __restrict__ out)
{
    extern __shared__ char smc[];
    const unsigned smb = smaddr(smc);
    float* coef = (float*)(smc + SM_CF);
    const int tid = threadIdx.x, wid = tid >> 5, lane = tid & 31;
    const int g = lane >> 2, t = lane & 3, r8 = lane & 7, quad = lane >> 3;
    const int ch = blockIdx.y, n = blockIdx.z;
    const int L0 = blockIdx.x * 64;
    const int C0 = ch * 128;

    #pragma unroll
    for (int k = 0; k < 8; k++) {
        int c = tid + 256 * k;
        int row = c >> 4, col8 = c & 15;
        cp16(smb + SM_WZF + row * OT_P + col8 * 16,
             g_wzf + (size_t)(C0 + row) * 128 + col8 * 8);
    }
    CP_COMMIT();

    if (tid < 64) {
        size_t b0 = (size_t)(n * KCH) * SEQ + L0 + tid;
        float m0 = g_mp[b0], m1 = g_mp[b0 + SEQ], m2 = g_mp[b0 + 2*SEQ];
        float M = fmaxf(m0, fmaxf(m1, m2));
        float w0 = ex2(m0 - M) * g_zp[b0];
        float w1 = ex2(m1 - M) * g_zp[b0 + SEQ];
        float w2 = ex2(m2 - M) * g_zp[b0 + 2*SEQ];
        float iZ = 1.0f / (w0 + w1 + w2);
        coef[tid] = w0*iZ; coef[64 + tid] = w1*iZ; coef[128 + tid] = w2*iZ;
    }
    __syncthreads();

    #pragma unroll
    for (int k = 0; k < 8; k++) {
        int idx = tid + 256 * k;
        int r = idx >> 5, c4 = idx & 31;
        size_t off = ((size_t)(n * KCH) * SEQ + L0 + r) * 128 + c4 * 4;
        uint2 ua = *(const uint2*)(g_ypart + off);
        uint2 ub = *(const uint2*)(g_ypart + off + (size_t)SEQ*128);
        uint2 uc = *(const uint2*)(g_ypart + off + (size_t)2*SEQ*128);
        float c0 = coef[r], c1 = coef[64 + r], c2 = coef[128 + r];
        float2 a0 = __half22float2(*(const __half2*)&ua.x);
        float2 a1 = __half22float2(*(const __half2*)&ua.y);
        float2 b0 = __half22float2(*(const __half2*)&ub.x);
        float2 b1 = __half22float2(*(const __half2*)&ub.y);
        float2 d0 = __half22float2(*(const __half2*)&uc.x);
        float2 d1 = __half22float2(*(const __half2*)&uc.y);
        float y0 = a0.x*c0 + b0.x*c1 + d0.x*c2, y1 = a0.y*c0 + b0.y*c1 + d0.y*c2;
        float y2 = a1.x*c0 + b1.x*c1 + d1.x*c2, y3 = a1.y*c0 + b1.y*c1 + d1.y*c2;
        *(uint2*)(smc + SM_YF + r * OT_P + c4 * 8) =
            make_uint2(packh2(y0, y1), packh2(y2, y3));
    }
    CP_WAIT(0);
    __syncthreads();

    float acc[8][4];
    #pragma unroll
    for (int j = 0; j < 8; j++)
        #pragma unroll
        for (int q = 0; q < 4; q++) acc[j][q] = 0.f;

    const unsigned aoff0 = (unsigned)(wid * 16 + r8 + (quad & 1) * 8) * OT_P + (unsigned)((quad >> 1) * 16);
    const unsigned boff0 = (unsigned)(r8 + (quad >> 1) * 8) * OT_P + (unsigned)((quad & 1) * 16);

    #pragma unroll
    for (int kk = 0; kk < 8; kk++) {
        unsigned Af[4];
        ldsm4(Af, smb + SM_WZF + aoff0 + kk * 32);
        #pragma unroll
        for (int nb = 0; nb < 4; nb++) {
            unsigned Bf[4];
            ldsm4(Bf, smb + SM_YF + boff0 + (unsigned)(nb * 16) * OT_P + kk * 32);
            mma_f16(acc[2*nb],   Af, Bf);
            mma_f16(acc[2*nb+1], Af, Bf + 2);
        }
    }

    {
        int c0 = C0 + wid * 16 + g;
        int c1 = c0 + 8;
        float b0 = __ldg(bz + c0), b1 = __ldg(bz + c1);
        const float* xr0 = x   + ((size_t)n * 256 + c0) * SEQ + L0;
        const float* xr1 = x   + ((size_t)n * 256 + c1) * SEQ + L0;
        float*       zr0 = out + ((size_t)n * 256 + c0) * SEQ + L0;
        float*       zr1 = out + ((size_t)n * 256 + c1) * SEQ + L0;
        #pragma unroll
        for (int j = 0; j < 8; j++) {
            int l = 8 * j + 2 * t;
            float2 xa = *(const float2*)(xr0 + l);
            float2 xb = *(const float2*)(xr1 + l);
            *(float2*)(zr0 + l) = make_float2(acc[j][0] + b0 + xa.x, acc[j][1] + b0 + xa.y);
            *(float2*)(zr1 + l) = make_float2(acc[j][2] + b1 + xb.x, acc[j][3] + b1 + xb.y);
        }
    }
}

// ---------------------------------------------------------------------------
extern "C" void kernel_launch(void* const* d_in, const int* in_sizes, int n_in,
                              void* d_out, int out_size)
{
    (void)in_sizes; (void)n_in; (void)out_size;
    const float* x  = (const float*)d_in[0];
    const float* gw = (const float*)d_in[1];
    const float* gb = (const float*)d_in[2];
    const float* tw = (const float*)d_in[3];
    const float* tb = (const float*)d_in[4];
    const float* pw = (const float*)d_in[5];
    const float* pb = (const float*)d_in[6];
    const float* zw = (const float*)d_in[7];
    const float* zb = (const float*)d_in[8];
    float* out = (float*)d_out;

    cudaFuncSetAttribute(proj_tc,     cudaFuncAttributeMaxDynamicSharedMemorySize, PROJ_SMEM);
    cudaFuncSetAttribute(attn_kernel, cudaFuncAttributeMaxDynamicSharedMemorySize, ATTN_SMEM);
    cudaFuncSetAttribute(out_tc,      cudaFuncAttributeMaxDynamicSharedMemorySize, OUT_SMEM);

    split_kernel<<<3264, 256>>>(x, gw, tw, pw, zw);
    proj_tc<<<dim3(49, 3, 2),       256, PROJ_SMEM>>>(gb, tb, pb);
    attn_kernel<<<dim3(49, KCH, 2), 256, ATTN_SMEM>>>();
    out_tc<<<dim3(98, 2, 2),        256, OUT_SMEM>>>(x, zb, out);
}

// round 15
// speedup vs baseline: 1.0070x; 1.0070x over previous
#include <cuda_runtime.h>
#include <cuda_bf16.h>
#include <cuda_fp16.h>

#define SEQ    6272
#define NKT    98      // total key tiles of 64
#define KCH    3       // key chunks (split-K)
#define LOG2E  1.44269504f

// ---------------- device scratch (allocation-free) ----------------
__device__ __align__(256) __nv_bfloat16 g_xh[2*256*SEQ], g_xl[2*256*SEQ];   // x split, (n,c,l)
__device__ __align__(256) __nv_bfloat16 g_wsh[3*128*256], g_wsl[3*128*256]; // g,theta,phi weights
__device__ __align__(256) __half       g_wzf[256*128];                       // wz single fp16
__device__ __align__(256) __nv_bfloat16 g_qh[2*SEQ*128], g_ql[2*SEQ*128];   // theta, (n,l,h)
__device__ __align__(256) __nv_bfloat16 g_kh[2*SEQ*128], g_kl[2*SEQ*128];   // phi * log2e, (n,l,h)
__device__ __align__(256) __half       g_vf[2*128*SEQ];                      // g, fp16, (n,h,l)
__device__ __align__(256) __half       g_ypart[2*KCH*SEQ*128];               // normalized partial y (fp16)
__device__ __align__(256) float g_zp[2*KCH*SEQ], g_mp[2*KCH*SEQ];            // partial Z, shift m (log2)

__device__ __forceinline__ unsigned smaddr(const void* p) {
    unsigned r;
    asm("{.reg .u64 t; cvta.to.shared.u64 t, %1; cvt.u32.u64 %0, t;}" : "=r"(r) : "l"(p));
    return r;
}
__device__ __forceinline__ void cp16(unsigned s, const void* g) {
    asm volatile("cp.async.cg.shared.global [%0], [%1], 16;" :: "r"(s), "l"(g) : "memory");
}
#define CP_COMMIT()  asm volatile("cp.async.commit_group;" ::: "memory")
#define CP_WAIT(N)   asm volatile("cp.async.wait_group %0;" :: "n"(N) : "memory")

__device__ __forceinline__ void ldsm4(unsigned* r, unsigned a) {
    asm volatile("ldmatrix.sync.aligned.m8n8.x4.shared.b16 {%0,%1,%2,%3}, [%4];"
        : "=r"(r[0]), "=r"(r[1]), "=r"(r[2]), "=r"(r[3]) : "r"(a));
}
__device__ __forceinline__ void ldsm4t(unsigned* r, unsigned a) {
    asm volatile("ldmatrix.sync.aligned.m8n8.x4.trans.shared.b16 {%0,%1,%2,%3}, [%4];"
        : "=r"(r[0]), "=r"(r[1]), "=r"(r[2]), "=r"(r[3]) : "r"(a));
}
__device__ __forceinline__ void mma_bf16(float* c, const unsigned* a, const unsigned* b) {
    asm volatile("mma.sync.aligned.m16n8k16.row.col.f32.bf16.bf16.f32 "
        "{%0,%1,%2,%3}, {%4,%5,%6,%7}, {%8,%9}, {%0,%1,%2,%3};"
        : "+f"(c[0]), "+f"(c[1]), "+f"(c[2]), "+f"(c[3])
        : "r"(a[0]), "r"(a[1]), "r"(a[2]), "r"(a[3]), "r"(b[0]), "r"(b[1]));
}
__device__ __forceinline__ void mma_f16(float* c, const unsigned* a, const unsigned* b) {
    asm volatile("mma.sync.aligned.m16n8k16.row.col.f32.f16.f16.f32 "
        "{%0,%1,%2,%3}, {%4,%5,%6,%7}, {%8,%9}, {%0,%1,%2,%3};"
        : "+f"(c[0]), "+f"(c[1]), "+f"(c[2]), "+f"(c[3])
        : "r"(a[0]), "r"(a[1]), "r"(a[2]), "r"(a[3]), "r"(b[0]), "r"(b[1]));
}
__device__ __forceinline__ void splitpack(float a, float b, unsigned &h, unsigned &l) {
    __nv_bfloat16 ha = __float2bfloat16(a), hb = __float2bfloat16(b);
    float la = a - __bfloat162float(ha), lb = b - __bfloat162float(hb);
    __nv_bfloat16 lA = __float2bfloat16(la), lB = __float2bfloat16(lb);
    h = (unsigned)__bfloat16_as_ushort(ha) | ((unsigned)__bfloat16_as_ushort(hb) << 16);
    l = (unsigned)__bfloat16_as_ushort(lA) | ((unsigned)__bfloat16_as_ushort(lB) << 16);
}
__device__ __forceinline__ unsigned packh2(float lo, float hi) {
    unsigned u;
    asm("cvt.rn.f16x2.f32 %0, %1, %2;" : "=r"(u) : "f"(hi), "f"(lo));
    return u;
}
__device__ __forceinline__ float ex2(float x) {
    float r;
    asm("ex2.approx.ftz.f32 %0, %1;" : "=f"(r) : "f"(x));
    return r;
}

// ---------------------------------------------------------------------------
// Kernel 0: split x + g/theta/phi weights into bf16 hi/lo; wz into fp16.
// ---------------------------------------------------------------------------
__global__ void __launch_bounds__(256) split_kernel(
    const float* __restrict__ x,
    const float* __restrict__ gw, const float* __restrict__ tw,
    const float* __restrict__ pw, const float* __restrict__ zw)
{
    const int bid = blockIdx.x, tid = threadIdx.x;
    if (bid < 3136) {
        int i = bid * 256 + tid;
        float4 v = ((const float4*)x)[i];
        unsigned h0, l0, h1, l1;
        splitpack(v.x, v.y, h0, l0);
        splitpack(v.z, v.w, h1, l1);
        *(uint2*)(g_xh + 4*(size_t)i) = make_uint2(h0, h1);
        *(uint2*)(g_xl + 4*(size_t)i) = make_uint2(l0, l1);
    } else {
        int j = (bid - 3136) * 256 + tid;
        int lj = j & 8191;
        if (j < 24576) {
            const float* src;
            __nv_bfloat16 *dh, *dl;
            if (j < 8192)       { src = gw; dh = g_wsh;           dl = g_wsl; }
            else if (j < 16384) { src = tw; dh = g_wsh + 32768;   dl = g_wsl + 32768; }
            else                { src = pw; dh = g_wsh + 65536;   dl = g_wsl + 65536; }
            float4 v = ((const float4*)src)[lj];
            unsigned h0, l0, h1, l1;
            splitpack(v.x, v.y, h0, l0);
            splitpack(v.z, v.w, h1, l1);
            *(uint2*)(dh + 4*lj) = make_uint2(h0, h1);
            *(uint2*)(dl + 4*lj) = make_uint2(l0, l1);
        } else {
            float4 v = ((const float4*)zw)[lj];
            *(uint2*)(g_wzf + 4*lj) = make_uint2(packh2(v.x, v.y), packh2(v.z, v.w));
        }
    }
}

// ---------------------------------------------------------------------------
// Kernel 1: projections on HMMA (3-pass bf16). Q out: bf16 hi/lo.
// K (pidx 2) out: bf16 hi/lo of (phi * log2e). V (pidx 0) out: fp16, (n,h,l).
// ---------------------------------------------------------------------------
#define PJ_XP 272
#define PJ_WP 144
#define SM_PX 0
#define SM_PW 69632
#define EP_P  272
#define PROJ_SMEM 143360

__global__ void __launch_bounds__(256, 1) proj_tc(
    const float* __restrict__ gb, const float* __restrict__ tb,
    const float* __restrict__ pb)
{
    extern __shared__ char smc[];
    const unsigned smb = smaddr(smc);
    const int tid = threadIdx.x, wid = tid >> 5, lane = tid & 31;
    const int g = lane >> 2, t = lane & 3, r8 = lane & 7, quad = lane >> 3;
    const int pidx = blockIdx.y, nn = blockIdx.z;
    const int L0 = blockIdx.x * 128;
    const int rw = wid * 16;

    const float* bias = (pidx == 0) ? gb : (pidx == 1) ? tb : pb;
    const __nv_bfloat16* Xh = g_xh + (size_t)nn * 256 * SEQ;
    const __nv_bfloat16* Xl = g_xl + (size_t)nn * 256 * SEQ;
    const __nv_bfloat16* Wh = g_wsh + pidx * 32768;
    const __nv_bfloat16* Wl = g_wsl + pidx * 32768;

    auto load_chunk = [&](int ck, int buf) {
        const unsigned xb = smb + SM_PX + buf * 34816;
        const unsigned wb = smb + SM_PW + buf * 36864;
        #pragma unroll
        for (int k = 0; k < 8; k++) {
            int c = tid + 256 * k;
            int half = c >> 10, cc = c & 1023;
            int row = cc >> 4, col8 = cc & 15;
            cp16(xb + half * 17408 + row * PJ_XP + col8 * 16,
                 (half ? Xl : Xh) + ((size_t)(ck * 64 + row)) * SEQ + L0 + col8 * 8);
        }
        #pragma unroll
        for (int k = 0; k < 8; k++) {
            int c = tid + 256 * k;
            int half = c >> 10, cc = c & 1023;
            int row = cc >> 3, col8 = cc & 7;
            cp16(wb + half * 18432 + row * PJ_WP + col8 * 16,
                 (half ? Wl : Wh) + (size_t)row * 256 + ck * 64 + col8 * 8);
        }
        CP_COMMIT();
    };

    load_chunk(0, 0);

    float s[16][4];
    #pragma unroll
    for (int i = 0; i < 16; i++)
        #pragma unroll
        for (int j = 0; j < 4; j++) s[i][j] = 0.f;

    const unsigned xt_rowA = (unsigned)((quad >> 1) * 8 + r8);
    const unsigned xt_colA = (unsigned)(rw + (quad & 1) * 8) * 2;
    const unsigned xt_rowB = (unsigned)((quad & 1) * 8 + r8);
    const unsigned wB_row = (unsigned)(r8 + (quad >> 1) * 8);
    const unsigned wB_col = (unsigned)((quad & 1) * 16);
    const unsigned wA_off0 = (unsigned)(rw + r8 + (quad & 1) * 8) * PJ_WP + (unsigned)((quad >> 1) * 16);

    for (int ck = 0; ck < 4; ck++) {
        const int b = ck & 1;
        if (ck + 1 < 4) { load_chunk(ck + 1, b ^ 1); CP_WAIT(1); }
        else            { CP_WAIT(0); }
        __syncthreads();

        const unsigned xh = smb + SM_PX + b * 34816, xl = xh + 17408;
        const unsigned wh = smb + SM_PW + b * 36864, wl = wh + 18432;

        if (pidx != 0) {
            #pragma unroll
            for (int kk = 0; kk < 4; kk++) {
                unsigned Ah[4], Al[4];
                unsigned aoff = (kk * 16 + xt_rowA) * PJ_XP + xt_colA;
                ldsm4t(Ah, xh + aoff);
                ldsm4t(Al, xl + aoff);
                #pragma unroll
                for (int nb = 0; nb < 8; nb++) {
                    unsigned Bh[4], Bl[4];
                    unsigned boff = (nb * 16 + wB_row) * PJ_WP + kk * 32 + wB_col;
                    ldsm4(Bh, wh + boff);
                    ldsm4(Bl, wl + boff);
                    mma_bf16(s[2*nb],   Ah, Bh);  mma_bf16(s[2*nb+1], Ah, Bh + 2);
                    mma_bf16(s[2*nb],   Ah, Bl);  mma_bf16(s[2*nb+1], Ah, Bl + 2);
                    mma_bf16(s[2*nb],   Al, Bh);  mma_bf16(s[2*nb+1], Al, Bh + 2);
                }
            }
        } else {
            #pragma unroll
            for (int kk = 0; kk < 4; kk++) {
                unsigned Ah[4], Al[4];
                unsigned aoff = wA_off0 + kk * 32;
                ldsm4(Ah, wh + aoff);
                ldsm4(Al, wl + aoff);
                #pragma unroll
                for (int nb = 0; nb < 8; nb++) {
                    unsigned Bh[4], Bl[4];
                    unsigned boff = (kk * 16 + xt_rowB) * PJ_XP + (nb * 16 + (quad >> 1) * 8) * 2;
                    ldsm4t(Bh, xh + boff);
                    ldsm4t(Bl, xl + boff);
                    mma_bf16(s[2*nb],   Ah, Bh);  mma_bf16(s[2*nb+1], Ah, Bh + 2);
                    mma_bf16(s[2*nb],   Ah, Bl);  mma_bf16(s[2*nb+1], Ah, Bl + 2);
                    mma_bf16(s[2*nb],   Al, Bh);  mma_bf16(s[2*nb+1], Al, Bh + 2);
                }
            }
        }
        __syncthreads();
    }

    if (pidx != 0) {
        // Q (pidx 1) plain; K (pidx 2) scaled by log2e so softmax uses bare ex2.
        const float sc = (pidx == 2) ? LOG2E : 1.0f;
        #pragma unroll
        for (int j = 0; j < 16; j++) {
            int h = 8 * j + 2 * t;
            float b0 = __ldg(bias + h), b1 = __ldg(bias + h + 1);
            unsigned hw, lw;
            splitpack((s[j][0] + b0) * sc, (s[j][1] + b1) * sc, hw, lw);
            *(unsigned*)(smc + (rw + g) * EP_P + h * 2)           = hw;
            *(unsigned*)(smc + 34816 + (rw + g) * EP_P + h * 2)   = lw;
            splitpack((s[j][2] + b0) * sc, (s[j][3] + b1) * sc, hw, lw);
            *(unsigned*)(smc + (rw + g + 8) * EP_P + h * 2)         = hw;
            *(unsigned*)(smc + 34816 + (rw + g + 8) * EP_P + h * 2) = lw;
        }
        __syncthreads();
        __nv_bfloat16* Dh = (pidx == 1) ? g_qh : g_kh;
        __nv_bfloat16* Dl = (pidx == 1) ? g_ql : g_kl;
        #pragma unroll
        for (int k = 0; k < 8; k++) {
            int idx = tid + 256 * k;
            int row = idx >> 4, c16 = idx & 15;
            size_t go = ((size_t)nn * SEQ + L0 + row) * 128 + c16 * 8;
            *(uint4*)(Dh + go) = *(const uint4*)(smc + row * EP_P + c16 * 16);
            *(uint4*)(Dl + go) = *(const uint4*)(smc + 34816 + row * EP_P + c16 * 16);
        }
    } else {
        // V: single fp16, rows = h, cols = l
        const int h0 = rw + g;
        float br0 = __ldg(bias + h0), br1 = __ldg(bias + h0 + 8);
        #pragma unroll
        for (int j = 0; j < 16; j++) {
            int l = 8 * j + 2 * t;
            *(unsigned*)(smc + h0 * EP_P + l * 2)       = packh2(s[j][0] + br0, s[j][1] + br0);
            *(unsigned*)(smc + (h0 + 8) * EP_P + l * 2) = packh2(s[j][2] + br1, s[j][3] + br1);
        }
        __syncthreads();
        #pragma unroll
        for (int k = 0; k < 8; k++) {
            int idx = tid + 256 * k;
            int row = idx >> 4, c16 = idx & 15;
            size_t go = ((size_t)nn * 128 + row) * SEQ + L0 + c16 * 8;
            *(uint4*)(g_vf + go) = *(const uint4*)(smc + row * EP_P + c16 * 16);
        }
    }
}

// ---------------------------------------------------------------------------
// Kernel 2: flash attention — R13 structure (single 64-key softmax per tile),
// log2-domain ex2 softmax + vote-skipped O rescale. QK 3-pass bf16, PV fp16.
// ---------------------------------------------------------------------------
#define QSTR 272
#define VSTR 144
#define SM_QH 0
#define SM_QL 34816
#define SM_K  69632        // 2 bufs x (hi 17408 + lo 17408)
#define SM_V  139264       // 2 bufs x 18432 (fp16 single)
#define ATTN_SMEM 176128

__device__ __forceinline__ void load_kv(
    unsigned smb, int jt, int buf, int tid,
    const __nv_bfloat16* Kh, const __nv_bfloat16* Kl,
    const __half* Vf)
{
    const unsigned kb = smb + SM_K + buf * 34816;
    const unsigned vb = smb + SM_V + buf * 18432;
    #pragma unroll
    for (int k = 0; k < 8; k++) {                 // K: 64 rows x 128ch, hi+lo
        int c = tid + 256 * k;
        int half = c >> 10, cc = c & 1023;
        int row = cc >> 4, col16 = cc & 15;
        cp16(kb + half * 17408 + row * QSTR + col16 * 16,
             (half ? Kl : Kh) + ((size_t)(jt * 64 + row)) * 128 + col16 * 8);
    }
    #pragma unroll
    for (int k = 0; k < 4; k++) {                 // V^T fp16: 128 rows(ch) x 64 keys
        int c = tid + 256 * k;
        int row = c >> 3, col = c & 7;
        cp16(vb + row * VSTR + col * 16,
             Vf + (size_t)row * SEQ + jt * 64 + col * 8);
    }
}

__global__ void __launch_bounds__(256, 1) attn_kernel()
{
    extern __shared__ char smc[];
    const unsigned smb = smaddr(smc);
    const int tid = threadIdx.x, wid = tid >> 5, lane = tid & 31;
    const int g = lane >> 2, t = lane & 3, r8 = lane & 7, quad = lane >> 3;
    const int kc = blockIdx.y, n = blockIdx.z, q0 = blockIdx.x * 128;
    const int start = kc * 33;
    const int cnt = (kc == KCH - 1) ? (NKT - 33 * (KCH - 1)) : 33;
    const int rw = wid * 16;

    const __nv_bfloat16* Qh = g_qh + (size_t)n * SEQ * 128;
    const __nv_bfloat16* Ql = g_ql + (size_t)n * SEQ * 128;
    const __nv_bfloat16* Kh = g_kh + (size_t)n * SEQ * 128;
    const __nv_bfloat16* Kl = g_kl + (size_t)n * SEQ * 128;
    const __half*        Vf = g_vf + (size_t)n * 128 * SEQ;

    const unsigned qa_off = (unsigned)(rw + r8 + (quad & 1) * 8) * QSTR + (unsigned)(quad >> 1) * 16;
    const unsigned kb_off = (unsigned)(r8 + (quad >> 1) * 8) * QSTR + (unsigned)(quad & 1) * 16;
    const unsigned vb_off = (unsigned)(r8 + (quad >> 1) * 8) * VSTR + (unsigned)(quad & 1) * 16;

    #pragma unroll
    for (int k = 0; k < 16; k++) {
        int c = tid + 256 * k;
        int half = c >> 11, cc = c & 2047;
        int row = cc >> 4, col16 = cc & 15;
        cp16(smb + (half ? SM_QL : SM_QH) + row * QSTR + col16 * 16,
             (half ? Ql : Qh) + ((size_t)(q0 + row)) * 128 + col16 * 8);
    }
    load_kv(smb, start, 0, tid, Kh, Kl, Vf);
    CP_COMMIT();

    float o[16][4];
    #pragma unroll
    for (int i = 0; i < 16; i++)
        #pragma unroll
        for (int j = 0; j < 4; j++) o[i][j] = 0.f;
    float z0 = 0.f, z1 = 0.f, m0 = -1e30f, m1 = -1e30f;

    for (int it = 0; it < cnt; it++) {
        const int b = it & 1;
        if (it + 1 < cnt) {
            load_kv(smb, start + it + 1, b ^ 1, tid, Kh, Kl, Vf);
            CP_COMMIT();
            CP_WAIT(1);
        } else {
            CP_WAIT(0);
        }
        __syncthreads();

        float s[8][4];
        #pragma unroll
        for (int i = 0; i < 8; i++)
            #pragma unroll
            for (int j = 0; j < 4; j++) s[i][j] = 0.f;

        const unsigned kbh = smb + SM_K + b * 34816;
        const unsigned kbl = kbh + 17408;
        #pragma unroll
        for (int kk = 0; kk < 8; kk++) {
            unsigned Ah[4], Al[4];
            ldsm4(Ah, smb + SM_QH + qa_off + kk * 32);
            ldsm4(Al, smb + SM_QL + qa_off + kk * 32);
            #pragma unroll
            for (int np = 0; np < 4; np++) {
                unsigned Bh[4], Bl[4];
                unsigned off = kb_off + (unsigned)np * (16 * QSTR) + kk * 32;
                ldsm4(Bh, kbh + off);
                ldsm4(Bl, kbl + off);
                mma_bf16(s[2*np],   Ah, Bh);   mma_bf16(s[2*np+1], Ah, Bh + 2);
                mma_bf16(s[2*np],   Ah, Bl);   mma_bf16(s[2*np+1], Ah, Bl + 2);
                mma_bf16(s[2*np],   Al, Bh);   mma_bf16(s[2*np+1], Al, Bh + 2);
            }
        }

        // ---- online softmax (log2 domain, ex2, vote-skipped rescale) ----
        {
            float a0 = -1e30f, a1 = -1e30f;
            #pragma unroll
            for (int i = 0; i < 8; i++) {
                a0 = fmaxf(a0, fmaxf(s[i][0], s[i][1]));
                a1 = fmaxf(a1, fmaxf(s[i][2], s[i][3]));
            }
            a0 = fmaxf(a0, __shfl_xor_sync(0xffffffffu, a0, 1));
            a0 = fmaxf(a0, __shfl_xor_sync(0xffffffffu, a0, 2));
            a1 = fmaxf(a1, __shfl_xor_sync(0xffffffffu, a1, 1));
            a1 = fmaxf(a1, __shfl_xor_sync(0xffffffffu, a1, 2));
            float mn0 = fmaxf(m0, a0), mn1 = fmaxf(m1, a1);
            float al0 = ex2(m0 - mn0), al1 = ex2(m1 - mn1);
            m0 = mn0; m1 = mn1;
            if (!__all_sync(0xffffffffu, (al0 == 1.0f) && (al1 == 1.0f))) {
                z0 *= al0; z1 *= al1;
                #pragma unroll
                for (int ct = 0; ct < 16; ct++) {
                    o[ct][0] *= al0; o[ct][1] *= al0;
                    o[ct][2] *= al1; o[ct][3] *= al1;
                }
            }
        }
        #pragma unroll
        for (int i = 0; i < 8; i++) {
            float p0 = ex2(s[i][0] - m0), p1 = ex2(s[i][1] - m0);
            float p2 = ex2(s[i][2] - m1), p3 = ex2(s[i][3] - m1);
            s[i][0] = p0; s[i][1] = p1; s[i][2] = p2; s[i][3] = p3;
            z0 += p0 + p1; z1 += p2 + p3;
        }

        // ---- PV: single-pass fp16 ----
        const unsigned vbf = smb + SM_V + b * 18432;
        #pragma unroll
        for (int kk = 0; kk < 4; kk++) {
            unsigned Af[4];
            Af[0] = packh2(s[2*kk][0],   s[2*kk][1]);
            Af[1] = packh2(s[2*kk][2],   s[2*kk][3]);
            Af[2] = packh2(s[2*kk+1][0], s[2*kk+1][1]);
            Af[3] = packh2(s[2*kk+1][2], s[2*kk+1][3]);
            #pragma unroll
            for (int cp = 0; cp < 8; cp++) {
                unsigned Bf[4];
                ldsm4(Bf, vbf + vb_off + (unsigned)cp * (16 * VSTR) + kk * 32);
                mma_f16(o[2*cp],   Af, Bf);
                mma_f16(o[2*cp+1], Af, Bf + 2);
            }
        }
        __syncthreads();
    }

    z0 += __shfl_xor_sync(0xffffffffu, z0, 1);
    z0 += __shfl_xor_sync(0xffffffffu, z0, 2);
    z1 += __shfl_xor_sync(0xffffffffu, z1, 1);
    z1 += __shfl_xor_sync(0xffffffffu, z1, 2);
    const float i0 = 1.0f / z0, i1 = 1.0f / z1;

    const size_t rbase = ((size_t)(n * KCH + kc)) * SEQ + q0 + rw + g;
    __half* y0 = g_ypart + rbase * 128;
    __half* y1 = y0 + 8 * 128;
    #pragma unroll
    for (int ct = 0; ct < 16; ct++) {
        int col = 8 * ct + 2 * t;
        *(unsigned*)(y0 + col) = packh2(o[ct][0] * i0, o[ct][1] * i0);
        *(unsigned*)(y1 + col) = packh2(o[ct][2] * i1, o[ct][3] * i1);
    }
    if (t == 0) {
        g_zp[rbase]     = z0;  g_mp[rbase]     = m0;
        g_zp[rbase + 8] = z1;  g_mp[rbase + 8] = m1;
    }
}

// ---------------------------------------------------------------------------
// Kernel 3: combine normalized fp16 partials + output projection (fp16 MMA).
// coef_i = 2^(m_i - M) * z_i / Z  (m in log2 domain).
// ---------------------------------------------------------------------------
#define OT_P 272
#define SM_WZF 0
#define SM_YF  34816
#define SM_CF  52224
#define OUT_SMEM 52992

__global__ void __launch_bounds__(256, 2) out_tc(
    const float* __restrict__ x, const float* __restrict__ bz,
    float* __restrict__ out)
{
    extern __shared__ char smc[];
    const unsigned smb = smaddr(smc);
    float* coef = (float*)(smc + SM_CF);
    const int tid = threadIdx.x, wid = tid >> 5, lane = tid & 31;
    const int g = lane >> 2, t = lane & 3, r8 = lane & 7, quad = lane >> 3;
    const int ch = blockIdx.y, n = blockIdx.z;
    const int L0 = blockIdx.x * 64;
    const int C0 = ch * 128;

    #pragma unroll
    for (int k = 0; k < 8; k++) {
        int c = tid + 256 * k;
        int row = c >> 4, col8 = c & 15;
        cp16(smb + SM_WZF + row * OT_P + col8 * 16,
             g_wzf + (size_t)(C0 + row) * 128 + col8 * 8);
    }
    CP_COMMIT();

    if (tid < 64) {
        size_t b0 = (size_t)(n * KCH) * SEQ + L0 + tid;
        float m0 = g_mp[b0], m1 = g_mp[b0 + SEQ], m2 = g_mp[b0 + 2*SEQ];
        float M = fmaxf(m0, fmaxf(m1, m2));
        float w0 = ex2(m0 - M) * g_zp[b0];
        float w1 = ex2(m1 - M) * g_zp[b0 + SEQ];
        float w2 = ex2(m2 - M) * g_zp[b0 + 2*SEQ];
        float iZ = 1.0f / (w0 + w1 + w2);
        coef[tid] = w0*iZ; coef[64 + tid] = w1*iZ; coef[128 + tid] = w2*iZ;
    }
    __syncthreads();

    #pragma unroll
    for (int k = 0; k < 8; k++) {
        int idx = tid + 256 * k;
        int r = idx >> 5, c4 = idx & 31;
        size_t off = ((size_t)(n * KCH) * SEQ + L0 + r) * 128 + c4 * 4;
        uint2 ua = *(const uint2*)(g_ypart + off);
        uint2 ub = *(const uint2*)(g_ypart + off + (size_t)SEQ*128);
        uint2 uc = *(const uint2*)(g_ypart + off + (size_t)2*SEQ*128);
        float c0 = coef[r], c1 = coef[64 + r], c2 = coef[128 + r];
        float2 a0 = __half22float2(*(const __half2*)&ua.x);
        float2 a1 = __half22float2(*(const __half2*)&ua.y);
        float2 b0 = __half22float2(*(const __half2*)&ub.x);
        float2 b1 = __half22float2(*(const __half2*)&ub.y);
        float2 d0 = __half22float2(*(const __half2*)&uc.x);
        float2 d1 = __half22float2(*(const __half2*)&uc.y);
        float y0 = a0.x*c0 + b0.x*c1 + d0.x*c2, y1 = a0.y*c0 + b0.y*c1 + d0.y*c2;
        float y2 = a1.x*c0 + b1.x*c1 + d1.x*c2, y3 = a1.y*c0 + b1.y*c1 + d1.y*c2;
        *(uint2*)(smc + SM_YF + r * OT_P + c4 * 8) =
            make_uint2(packh2(y0, y1), packh2(y2, y3));
    }
    CP_WAIT(0);
    __syncthreads();

    float acc[8][4];
    #pragma unroll
    for (int j = 0; j < 8; j++)
        #pragma unroll
        for (int q = 0; q < 4; q++) acc[j][q] = 0.f;

    const unsigned aoff0 = (unsigned)(wid * 16 + r8 + (quad & 1) * 8) * OT_P + (unsigned)((quad >> 1) * 16);
    const unsigned boff0 = (unsigned)(r8 + (quad >> 1) * 8) * OT_P + (unsigned)((quad & 1) * 16);

    #pragma unroll
    for (int kk = 0; kk < 8; kk++) {
        unsigned Af[4];
        ldsm4(Af, smb + SM_WZF + aoff0 + kk * 32);
        #pragma unroll
        for (int nb = 0; nb < 4; nb++) {
            unsigned Bf[4];
            ldsm4(Bf, smb + SM_YF + boff0 + (unsigned)(nb * 16) * OT_P + kk * 32);
            mma_f16(acc[2*nb],   Af, Bf);
            mma_f16(acc[2*nb+1], Af, Bf + 2);
        }
    }

    {
        int c0 = C0 + wid * 16 + g;
        int c1 = c0 + 8;
        float b0 = __ldg(bz + c0), b1 = __ldg(bz + c1);
        const float* xr0 = x   + ((size_t)n * 256 + c0) * SEQ + L0;
        const float* xr1 = x   + ((size_t)n * 256 + c1) * SEQ + L0;
        float*       zr0 = out + ((size_t)n * 256 + c0) * SEQ + L0;
        float*       zr1 = out + ((size_t)n * 256 + c1) * SEQ + L0;
        #pragma unroll
        for (int j = 0; j < 8; j++) {
            int l = 8 * j + 2 * t;
            float2 xa = *(const float2*)(xr0 + l);
            float2 xb = *(const float2*)(xr1 + l);
            *(float2*)(zr0 + l) = make_float2(acc[j][0] + b0 + xa.x, acc[j][1] + b0 + xa.y);
            *(float2*)(zr1 + l) = make_float2(acc[j][2] + b1 + xb.x, acc[j][3] + b1 + xb.y);
        }
    }
}

// ---------------------------------------------------------------------------
extern "C" void kernel_launch(void* const* d_in, const int* in_sizes, int n_in,
                              void* d_out, int out_size)
{
    (void)in_sizes; (void)n_in; (void)out_size;
    const float* x  = (const float*)d_in[0];
    const float* gw = (const float*)d_in[1];
    const float* gb = (const float*)d_in[2];
    const float* tw = (const float*)d_in[3];
    const float* tb = (const float*)d_in[4];
    const float* pw = (const float*)d_in[5];
    const float* pb = (const float*)d_in[6];
    const float* zw = (const float*)d_in[7];
    const float* zb = (const float*)d_in[8];
    float* out = (float*)d_out;

    cudaFuncSetAttribute(proj_tc,     cudaFuncAttributeMaxDynamicSharedMemorySize, PROJ_SMEM);
    cudaFuncSetAttribute(attn_kernel, cudaFuncAttributeMaxDynamicSharedMemorySize, ATTN_SMEM);
    cudaFuncSetAttribute(out_tc,      cudaFuncAttributeMaxDynamicSharedMemorySize, OUT_SMEM);

    split_kernel<<<3264, 256>>>(x, gw, tw, pw, zw);
    proj_tc<<<dim3(49, 3, 2),       256, PROJ_SMEM>>>(gb, tb, pb);
    attn_kernel<<<dim3(49, KCH, 2), 256, ATTN_SMEM>>>();
    out_tc<<<dim3(98, 2, 2),        256, OUT_SMEM>>>(x, zb, out);
}

// round 16
// speedup vs baseline: 1.0177x; 1.0106x over previous
#include <cuda_runtime.h>
#include <cuda_bf16.h>
#include <cuda_fp16.h>

#define SEQ    6272
#define NKT    98      // total key tiles of 64
#define KCH    3       // key chunks (split-K)
#define LOG2E  1.44269504f

// ---------------- device scratch (allocation-free) ----------------
__device__ __align__(256) __nv_bfloat16 g_xh[2*256*SEQ], g_xl[2*256*SEQ];   // x split, (n,c,l)
__device__ __align__(256) __nv_bfloat16 g_wsh[3*128*256], g_wsl[3*128*256]; // g,theta,phi weights
__device__ __align__(256) __half       g_wzf[256*128];                       // wz single fp16
__device__ __align__(256) __nv_bfloat16 g_qh[2*SEQ*128], g_ql[2*SEQ*128];   // theta, (n,l,h)
__device__ __align__(256) __nv_bfloat16 g_kh[2*SEQ*128], g_kl[2*SEQ*128];   // phi * log2e, (n,l,h)
__device__ __align__(256) __half       g_vf[2*128*SEQ];                      // g, fp16, (n,h,l)
__device__ __align__(256) __half       g_ypart[2*KCH*SEQ*128];               // normalized partial y (fp16)
__device__ __align__(256) float g_zp[2*KCH*SEQ], g_mp[2*KCH*SEQ];            // partial Z, shift m (log2)

__device__ __forceinline__ unsigned smaddr(const void* p) {
    unsigned r;
    asm("{.reg .u64 t; cvta.to.shared.u64 t, %1; cvt.u32.u64 %0, t;}" : "=r"(r) : "l"(p));
    return r;
}
__device__ __forceinline__ void cp16(unsigned s, const void* g) {
    asm volatile("cp.async.cg.shared.global [%0], [%1], 16;" :: "r"(s), "l"(g) : "memory");
}
#define CP_COMMIT()  asm volatile("cp.async.commit_group;" ::: "memory")
#define CP_WAIT(N)   asm volatile("cp.async.wait_group %0;" :: "n"(N) : "memory")

__device__ __forceinline__ void ldsm4(unsigned* r, unsigned a) {
    asm volatile("ldmatrix.sync.aligned.m8n8.x4.shared.b16 {%0,%1,%2,%3}, [%4];"
        : "=r"(r[0]), "=r"(r[1]), "=r"(r[2]), "=r"(r[3]) : "r"(a));
}
__device__ __forceinline__ void ldsm4t(unsigned* r, unsigned a) {
    asm volatile("ldmatrix.sync.aligned.m8n8.x4.trans.shared.b16 {%0,%1,%2,%3}, [%4];"
        : "=r"(r[0]), "=r"(r[1]), "=r"(r[2]), "=r"(r[3]) : "r"(a));
}
__device__ __forceinline__ void mma_bf16(float* c, const unsigned* a, const unsigned* b) {
    asm volatile("mma.sync.aligned.m16n8k16.row.col.f32.bf16.bf16.f32 "
        "{%0,%1,%2,%3}, {%4,%5,%6,%7}, {%8,%9}, {%0,%1,%2,%3};"
        : "+f"(c[0]), "+f"(c[1]), "+f"(c[2]), "+f"(c[3])
        : "r"(a[0]), "r"(a[1]), "r"(a[2]), "r"(a[3]), "r"(b[0]), "r"(b[1]));
}
__device__ __forceinline__ void mma_f16(float* c, const unsigned* a, const unsigned* b) {
    asm volatile("mma.sync.aligned.m16n8k16.row.col.f32.f16.f16.f32 "
        "{%0,%1,%2,%3}, {%4,%5,%6,%7}, {%8,%9}, {%0,%1,%2,%3};"
        : "+f"(c[0]), "+f"(c[1]), "+f"(c[2]), "+f"(c[3])
        : "r"(a[0]), "r"(a[1]), "r"(a[2]), "r"(a[3]), "r"(b[0]), "r"(b[1]));
}
__device__ __forceinline__ void splitpack(float a, float b, unsigned &h, unsigned &l) {
    __nv_bfloat16 ha = __float2bfloat16(a), hb = __float2bfloat16(b);
    float la = a - __bfloat162float(ha), lb = b - __bfloat162float(hb);
    __nv_bfloat16 lA = __float2bfloat16(la), lB = __float2bfloat16(lb);
    h = (unsigned)__bfloat16_as_ushort(ha) | ((unsigned)__bfloat16_as_ushort(hb) << 16);
    l = (unsigned)__bfloat16_as_ushort(lA) | ((unsigned)__bfloat16_as_ushort(lB) << 16);
}
__device__ __forceinline__ unsigned packh2(float lo, float hi) {
    unsigned u;
    asm("cvt.rn.f16x2.f32 %0, %1, %2;" : "=r"(u) : "f"(hi), "f"(lo));
    return u;
}
__device__ __forceinline__ float ex2(float x) {
    float r;
    asm("ex2.approx.ftz.f32 %0, %1;" : "=f"(r) : "f"(x));
    return r;
}
__device__ __forceinline__ unsigned ex2h2(unsigned x) {
    unsigned r;
    asm("ex2.approx.f16x2 %0, %1;" : "=r"(r) : "r"(x));
    return r;
}

// ---------------------------------------------------------------------------
// Kernel 0: split x + g/theta/phi weights into bf16 hi/lo; wz into fp16.
// ---------------------------------------------------------------------------
__global__ void __launch_bounds__(256) split_kernel(
    const float* __restrict__ x,
    const float* __restrict__ gw, const float* __restrict__ tw,
    const float* __restrict__ pw, const float* __restrict__ zw)
{
    const int bid = blockIdx.x, tid = threadIdx.x;
    if (bid < 3136) {
        int i = bid * 256 + tid;
        float4 v = ((const float4*)x)[i];
        unsigned h0, l0, h1, l1;
        splitpack(v.x, v.y, h0, l0);
        splitpack(v.z, v.w, h1, l1);
        *(uint2*)(g_xh + 4*(size_t)i) = make_uint2(h0, h1);
        *(uint2*)(g_xl + 4*(size_t)i) = make_uint2(l0, l1);
    } else {
        int j = (bid - 3136) * 256 + tid;
        int lj = j & 8191;
        if (j < 24576) {
            const float* src;
            __nv_bfloat16 *dh, *dl;
            if (j < 8192)       { src = gw; dh = g_wsh;           dl = g_wsl; }
            else if (j < 16384) { src = tw; dh = g_wsh + 32768;   dl = g_wsl + 32768; }
            else                { src = pw; dh = g_wsh + 65536;   dl = g_wsl + 65536; }
            float4 v = ((const float4*)src)[lj];
            unsigned h0, l0, h1, l1;
            splitpack(v.x, v.y, h0, l0);
            splitpack(v.z, v.w, h1, l1);
            *(uint2*)(dh + 4*lj) = make_uint2(h0, h1);
            *(uint2*)(dl + 4*lj) = make_uint2(l0, l1);
        } else {
            float4 v = ((const float4*)zw)[lj];
            *(uint2*)(g_wzf + 4*lj) = make_uint2(packh2(v.x, v.y), packh2(v.z, v.w));
        }
    }
}

// ---------------------------------------------------------------------------
// Kernel 1: projections on HMMA (3-pass bf16). Q out: bf16 hi/lo.
// K (pidx 2) out: bf16 hi/lo of (phi * log2e). V (pidx 0) out: fp16, (n,h,l).
// ---------------------------------------------------------------------------
#define PJ_XP 272
#define PJ_WP 144
#define SM_PX 0
#define SM_PW 69632
#define EP_P  272
#define PROJ_SMEM 143360

__global__ void __launch_bounds__(256, 1) proj_tc(
    const float* __restrict__ gb, const float* __restrict__ tb,
    const float* __restrict__ pb)
{
    extern __shared__ char smc[];
    const unsigned smb = smaddr(smc);
    const int tid = threadIdx.x, wid = tid >> 5, lane = tid & 31;
    const int g = lane >> 2, t = lane & 3, r8 = lane & 7, quad = lane >> 3;
    const int pidx = blockIdx.y, nn = blockIdx.z;
    const int L0 = blockIdx.x * 128;
    const int rw = wid * 16;

    const float* bias = (pidx == 0) ? gb : (pidx == 1) ? tb : pb;
    const __nv_bfloat16* Xh = g_xh + (size_t)nn * 256 * SEQ;
    const __nv_bfloat16* Xl = g_xl + (size_t)nn * 256 * SEQ;
    const __nv_bfloat16* Wh = g_wsh + pidx * 32768;
    const __nv_bfloat16* Wl = g_wsl + pidx * 32768;

    auto load_chunk = [&](int ck, int buf) {
        const unsigned xb = smb + SM_PX + buf * 34816;
        const unsigned wb = smb + SM_PW + buf * 36864;
        #pragma unroll
        for (int k = 0; k < 8; k++) {
            int c = tid + 256 * k;
            int half = c >> 10, cc = c & 1023;
            int row = cc >> 4, col8 = cc & 15;
            cp16(xb + half * 17408 + row * PJ_XP + col8 * 16,
                 (half ? Xl : Xh) + ((size_t)(ck * 64 + row)) * SEQ + L0 + col8 * 8);
        }
        #pragma unroll
        for (int k = 0; k < 8; k++) {
            int c = tid + 256 * k;
            int half = c >> 10, cc = c & 1023;
            int row = cc >> 3, col8 = cc & 7;
            cp16(wb + half * 18432 + row * PJ_WP + col8 * 16,
                 (half ? Wl : Wh) + (size_t)row * 256 + ck * 64 + col8 * 8);
        }
        CP_COMMIT();
    };

    load_chunk(0, 0);

    float s[16][4];
    #pragma unroll
    for (int i = 0; i < 16; i++)
        #pragma unroll
        for (int j = 0; j < 4; j++) s[i][j] = 0.f;

    const unsigned xt_rowA = (unsigned)((quad >> 1) * 8 + r8);
    const unsigned xt_colA = (unsigned)(rw + (quad & 1) * 8) * 2;
    const unsigned xt_rowB = (unsigned)((quad & 1) * 8 + r8);
    const unsigned wB_row = (unsigned)(r8 + (quad >> 1) * 8);
    const unsigned wB_col = (unsigned)((quad & 1) * 16);
    const unsigned wA_off0 = (unsigned)(rw + r8 + (quad & 1) * 8) * PJ_WP + (unsigned)((quad >> 1) * 16);

    for (int ck = 0; ck < 4; ck++) {
        const int b = ck & 1;
        if (ck + 1 < 4) { load_chunk(ck + 1, b ^ 1); CP_WAIT(1); }
        else            { CP_WAIT(0); }
        __syncthreads();

        const unsigned xh = smb + SM_PX + b * 34816, xl = xh + 17408;
        const unsigned wh = smb + SM_PW + b * 36864, wl = wh + 18432;

        if (pidx != 0) {
            #pragma unroll
            for (int kk = 0; kk < 4; kk++) {
                unsigned Ah[4], Al[4];
                unsigned aoff = (kk * 16 + xt_rowA) * PJ_XP + xt_colA;
                ldsm4t(Ah, xh + aoff);
                ldsm4t(Al, xl + aoff);
                #pragma unroll
                for (int nb = 0; nb < 8; nb++) {
                    unsigned Bh[4], Bl[4];
                    unsigned boff = (nb * 16 + wB_row) * PJ_WP + kk * 32 + wB_col;
                    ldsm4(Bh, wh + boff);
                    ldsm4(Bl, wl + boff);
                    mma_bf16(s[2*nb],   Ah, Bh);  mma_bf16(s[2*nb+1], Ah, Bh + 2);
                    mma_bf16(s[2*nb],   Ah, Bl);  mma_bf16(s[2*nb+1], Ah, Bl + 2);
                    mma_bf16(s[2*nb],   Al, Bh);  mma_bf16(s[2*nb+1], Al, Bh + 2);
                }
            }
        } else {
            #pragma unroll
            for (int kk = 0; kk < 4; kk++) {
                unsigned Ah[4], Al[4];
                unsigned aoff = wA_off0 + kk * 32;
                ldsm4(Ah, wh + aoff);
                ldsm4(Al, wl + aoff);
                #pragma unroll
                for (int nb = 0; nb < 8; nb++) {
                    unsigned Bh[4], Bl[4];
                    unsigned boff = (kk * 16 + xt_rowB) * PJ_XP + (nb * 16 + (quad >> 1) * 8) * 2;
                    ldsm4t(Bh, xh + boff);
                    ldsm4t(Bl, xl + boff);
                    mma_bf16(s[2*nb],   Ah, Bh);  mma_bf16(s[2*nb+1], Ah, Bh + 2);
                    mma_bf16(s[2*nb],   Ah, Bl);  mma_bf16(s[2*nb+1], Ah, Bl + 2);
                    mma_bf16(s[2*nb],   Al, Bh);  mma_bf16(s[2*nb+1], Al, Bh + 2);
                }
            }
        }
        __syncthreads();
    }

    if (pidx != 0) {
        // Q (pidx 1) plain; K (pidx 2) scaled by log2e so softmax uses bare ex2.
        const float sc = (pidx == 2) ? LOG2E : 1.0f;
        #pragma unroll
        for (int j = 0; j < 16; j++) {
            int h = 8 * j + 2 * t;
            float b0 = __ldg(bias + h), b1 = __ldg(bias + h + 1);
            unsigned hw, lw;
            splitpack((s[j][0] + b0) * sc, (s[j][1] + b1) * sc, hw, lw);
            *(unsigned*)(smc + (rw + g) * EP_P + h * 2)           = hw;
            *(unsigned*)(smc + 34816 + (rw + g) * EP_P + h * 2)   = lw;
            splitpack((s[j][2] + b0) * sc, (s[j][3] + b1) * sc, hw, lw);
            *(unsigned*)(smc + (rw + g + 8) * EP_P + h * 2)         = hw;
            *(unsigned*)(smc + 34816 + (rw + g + 8) * EP_P + h * 2) = lw;
        }
        __syncthreads();
        __nv_bfloat16* Dh = (pidx == 1) ? g_qh : g_kh;
        __nv_bfloat16* Dl = (pidx == 1) ? g_ql : g_kl;
        #pragma unroll
        for (int k = 0; k < 8; k++) {
            int idx = tid + 256 * k;
            int row = idx >> 4, c16 = idx & 15;
            size_t go = ((size_t)nn * SEQ + L0 + row) * 128 + c16 * 8;
            *(uint4*)(Dh + go) = *(const uint4*)(smc + row * EP_P + c16 * 16);
            *(uint4*)(Dl + go) = *(const uint4*)(smc + 34816 + row * EP_P + c16 * 16);
        }
    } else {
        // V: single fp16, rows = h, cols = l
        const int h0 = rw + g;
        float br0 = __ldg(bias + h0), br1 = __ldg(bias + h0 + 8);
        #pragma unroll
        for (int j = 0; j < 16; j++) {
            int l = 8 * j + 2 * t;
            *(unsigned*)(smc + h0 * EP_P + l * 2)       = packh2(s[j][0] + br0, s[j][1] + br0);
            *(unsigned*)(smc + (h0 + 8) * EP_P + l * 2) = packh2(s[j][2] + br1, s[j][3] + br1);
        }
        __syncthreads();
        #pragma unroll
        for (int k = 0; k < 8; k++) {
            int idx = tid + 256 * k;
            int row = idx >> 4, c16 = idx & 15;
            size_t go = ((size_t)nn * 128 + row) * SEQ + L0 + c16 * 8;
            *(uint4*)(g_vf + go) = *(const uint4*)(smc + row * EP_P + c16 * 16);
        }
    }
}

// ---------------------------------------------------------------------------
// Kernel 2: flash attention — QK 3-pass bf16 (log2 domain), PV fp16.
// NEW: Q fragments hoisted into registers (loaded once at tile 0);
//      exponentials via ex2.approx.f16x2 producing the packed-fp16 P
//      A-fragments directly (MUFU issues halved).
// ---------------------------------------------------------------------------
#define QSTR 272
#define VSTR 144
#define SM_QH 0
#define SM_QL 34816
#define SM_K  69632        // 2 bufs x (hi 17408 + lo 17408)
#define SM_V  139264       // 2 bufs x 18432 (fp16 single)
#define ATTN_SMEM 176128

__device__ __forceinline__ void load_kv(
    unsigned smb, int jt, int buf, int tid,
    const __nv_bfloat16* Kh, const __nv_bfloat16* Kl,
    const __half* Vf)
{
    const unsigned kb = smb + SM_K + buf * 34816;
    const unsigned vb = smb + SM_V + buf * 18432;
    #pragma unroll
    for (int k = 0; k < 8; k++) {                 // K: 64 rows x 128ch, hi+lo
        int c = tid + 256 * k;
        int half = c >> 10, cc = c & 1023;
        int row = cc >> 4, col16 = cc & 15;
        cp16(kb + half * 17408 + row * QSTR + col16 * 16,
             (half ? Kl : Kh) + ((size_t)(jt * 64 + row)) * 128 + col16 * 8);
    }
    #pragma unroll
    for (int k = 0; k < 4; k++) {                 // V^T fp16: 128 rows(ch) x 64 keys
        int c = tid + 256 * k;
        int row = c >> 3, col = c & 7;
        cp16(vb + row * VSTR + col * 16,
             Vf + (size_t)row * SEQ + jt * 64 + col * 8);
    }
}

__global__ void __launch_bounds__(256, 1) attn_kernel()
{
    extern __shared__ char smc[];
    const unsigned smb = smaddr(smc);
    const int tid = threadIdx.x, wid = tid >> 5, lane = tid & 31;
    const int g = lane >> 2, t = lane & 3, r8 = lane & 7, quad = lane >> 3;
    const int kc = blockIdx.y, n = blockIdx.z, q0 = blockIdx.x * 128;
    const int start = kc * 33;
    const int cnt = (kc == KCH - 1) ? (NKT - 33 * (KCH - 1)) : 33;
    const int rw = wid * 16;

    const __nv_bfloat16* Qh = g_qh + (size_t)n * SEQ * 128;
    const __nv_bfloat16* Ql = g_ql + (size_t)n * SEQ * 128;
    const __nv_bfloat16* Kh = g_kh + (size_t)n * SEQ * 128;
    const __nv_bfloat16* Kl = g_kl + (size_t)n * SEQ * 128;
    const __half*        Vf = g_vf + (size_t)n * 128 * SEQ;

    const unsigned qa_off = (unsigned)(rw + r8 + (quad & 1) * 8) * QSTR + (unsigned)(quad >> 1) * 16;
    const unsigned kb_off = (unsigned)(r8 + (quad >> 1) * 8) * QSTR + (unsigned)(quad & 1) * 16;
    const unsigned vb_off = (unsigned)(r8 + (quad >> 1) * 8) * VSTR + (unsigned)(quad & 1) * 16;

    #pragma unroll
    for (int k = 0; k < 16; k++) {
        int c = tid + 256 * k;
        int half = c >> 11, cc = c & 2047;
        int row = cc >> 4, col16 = cc & 15;
        cp16(smb + (half ? SM_QL : SM_QH) + row * QSTR + col16 * 16,
             (half ? Ql : Qh) + ((size_t)(q0 + row)) * 128 + col16 * 8);
    }
    load_kv(smb, start, 0, tid, Kh, Kl, Vf);
    CP_COMMIT();

    float o[16][4];
    #pragma unroll
    for (int i = 0; i < 16; i++)
        #pragma unroll
        for (int j = 0; j < 4; j++) o[i][j] = 0.f;
    float z0 = 0.f, z1 = 0.f, m0 = -1e30f, m1 = -1e30f;

    unsigned Aqh[8][4], Aql[8][4];   // Q fragments, loaded once, live all tiles

    for (int it = 0; it < cnt; it++) {
        const int b = it & 1;
        if (it + 1 < cnt) {
            load_kv(smb, start + it + 1, b ^ 1, tid, Kh, Kl, Vf);
            CP_COMMIT();
            CP_WAIT(1);
        } else {
            CP_WAIT(0);
        }
        __syncthreads();

        if (it == 0) {      // hoist Q fragments into registers (once)
            #pragma unroll
            for (int kk = 0; kk < 8; kk++) {
                ldsm4(Aqh[kk], smb + SM_QH + qa_off + kk * 32);
                ldsm4(Aql[kk], smb + SM_QL + qa_off + kk * 32);
            }
        }

        float s[8][4];
        #pragma unroll
        for (int i = 0; i < 8; i++)
            #pragma unroll
            for (int j = 0; j < 4; j++) s[i][j] = 0.f;

        const unsigned kbh = smb + SM_K + b * 34816;
        const unsigned kbl = kbh + 17408;
        #pragma unroll
        for (int kk = 0; kk < 8; kk++) {
            #pragma unroll
            for (int np = 0; np < 4; np++) {
                unsigned Bh[4], Bl[4];
                unsigned off = kb_off + (unsigned)np * (16 * QSTR) + kk * 32;
                ldsm4(Bh, kbh + off);
                ldsm4(Bl, kbl + off);
                mma_bf16(s[2*np],   Aqh[kk], Bh);   mma_bf16(s[2*np+1], Aqh[kk], Bh + 2);
                mma_bf16(s[2*np],   Aqh[kk], Bl);   mma_bf16(s[2*np+1], Aqh[kk], Bl + 2);
                mma_bf16(s[2*np],   Aql[kk], Bh);   mma_bf16(s[2*np+1], Aql[kk], Bh + 2);
            }
        }

        // ---- online softmax (log2 domain, vote-skipped rescale) ----
        {
            float a0 = -1e30f, a1 = -1e30f;
            #pragma unroll
            for (int i = 0; i < 8; i++) {
                a0 = fmaxf(a0, fmaxf(s[i][0], s[i][1]));
                a1 = fmaxf(a1, fmaxf(s[i][2], s[i][3]));
            }
            a0 = fmaxf(a0, __shfl_xor_sync(0xffffffffu, a0, 1));
            a0 = fmaxf(a0, __shfl_xor_sync(0xffffffffu, a0, 2));
            a1 = fmaxf(a1, __shfl_xor_sync(0xffffffffu, a1, 1));
            a1 = fmaxf(a1, __shfl_xor_sync(0xffffffffu, a1, 2));
            float mn0 = fmaxf(m0, a0), mn1 = fmaxf(m1, a1);
            float al0 = ex2(m0 - mn0), al1 = ex2(m1 - mn1);
            m0 = mn0; m1 = mn1;
            if (!__all_sync(0xffffffffu, (al0 == 1.0f) && (al1 == 1.0f))) {
                z0 *= al0; z1 *= al1;
                #pragma unroll
                for (int ct = 0; ct < 16; ct++) {
                    o[ct][0] *= al0; o[ct][1] *= al0;
                    o[ct][2] *= al1; o[ct][3] *= al1;
                }
            }
        }

        // ---- packed-fp16 exponentials: P fragments produced directly ----
        unsigned Pf[16];
        #pragma unroll
        for (int i = 0; i < 8; i++) {
            Pf[2*i]     = ex2h2(packh2(s[i][0] - m0, s[i][1] - m0));
            Pf[2*i + 1] = ex2h2(packh2(s[i][2] - m1, s[i][3] - m1));
            float2 f0 = __half22float2(*(const __half2*)&Pf[2*i]);
            float2 f1 = __half22float2(*(const __half2*)&Pf[2*i + 1]);
            z0 += f0.x + f0.y;
            z1 += f1.x + f1.y;
        }

        // ---- PV: single-pass fp16 ----
        const unsigned vbf = smb + SM_V + b * 18432;
        #pragma unroll
        for (int kk = 0; kk < 4; kk++) {
            #pragma unroll
            for (int cp = 0; cp < 8; cp++) {
                unsigned Bf[4];
                ldsm4(Bf, vbf + vb_off + (unsigned)cp * (16 * VSTR) + kk * 32);
                mma_f16(o[2*cp],   Pf + 4*kk, Bf);
                mma_f16(o[2*cp+1], Pf + 4*kk, Bf + 2);
            }
        }
        __syncthreads();
    }

    z0 += __shfl_xor_sync(0xffffffffu, z0, 1);
    z0 += __shfl_xor_sync(0xffffffffu, z0, 2);
    z1 += __shfl_xor_sync(0xffffffffu, z1, 1);
    z1 += __shfl_xor_sync(0xffffffffu, z1, 2);
    const float i0 = 1.0f / z0, i1 = 1.0f / z1;

    const size_t rbase = ((size_t)(n * KCH + kc)) * SEQ + q0 + rw + g;
    __half* y0 = g_ypart + rbase * 128;
    __half* y1 = y0 + 8 * 128;
    #pragma unroll
    for (int ct = 0; ct < 16; ct++) {
        int col = 8 * ct + 2 * t;
        *(unsigned*)(y0 + col) = packh2(o[ct][0] * i0, o[ct][1] * i0);
        *(unsigned*)(y1 + col) = packh2(o[ct][2] * i1, o[ct][3] * i1);
    }
    if (t == 0) {
        g_zp[rbase]     = z0;  g_mp[rbase]     = m0;
        g_zp[rbase + 8] = z1;  g_mp[rbase + 8] = m1;
    }
}

// ---------------------------------------------------------------------------
// Kernel 3: combine normalized fp16 partials + output projection (fp16 MMA).
// coef_i = 2^(m_i - M) * z_i / Z  (m in log2 domain).
// ---------------------------------------------------------------------------
#define OT_P 272
#define SM_WZF 0
#define SM_YF  34816
#define SM_CF  52224
#define OUT_SMEM 52992

__global__ void __launch_bounds__(256, 2) out_tc(
    const float* __restrict__ x, const float* __restrict__ bz,
    float* __restrict__ out)
{
    extern __shared__ char smc[];
    const unsigned smb = smaddr(smc);
    float* coef = (float*)(smc + SM_CF);
    const int tid = threadIdx.x, wid = tid >> 5, lane = tid & 31;
    const int g = lane >> 2, t = lane & 3, r8 = lane & 7, quad = lane >> 3;
    const int ch = blockIdx.y, n = blockIdx.z;
    const int L0 = blockIdx.x * 64;
    const int C0 = ch * 128;

    #pragma unroll
    for (int k = 0; k < 8; k++) {
        int c = tid + 256 * k;
        int row = c >> 4, col8 = c & 15;
        cp16(smb + SM_WZF + row * OT_P + col8 * 16,
             g_wzf + (size_t)(C0 + row) * 128 + col8 * 8);
    }
    CP_COMMIT();

    if (tid < 64) {
        size_t b0 = (size_t)(n * KCH) * SEQ + L0 + tid;
        float m0 = g_mp[b0], m1 = g_mp[b0 + SEQ], m2 = g_mp[b0 + 2*SEQ];
        float M = fmaxf(m0, fmaxf(m1, m2));
        float w0 = ex2(m0 - M) * g_zp[b0];
        float w1 = ex2(m1 - M) * g_zp[b0 + SEQ];
        float w2 = ex2(m2 - M) * g_zp[b0 + 2*SEQ];
        float iZ = 1.0f / (w0 + w1 + w2);
        coef[tid] = w0*iZ; coef[64 + tid] = w1*iZ; coef[128 + tid] = w2*iZ;
    }
    __syncthreads();

    #pragma unroll
    for (int k = 0; k < 8; k++) {
        int idx = tid + 256 * k;
        int r = idx >> 5, c4 = idx & 31;
        size_t off = ((size_t)(n * KCH) * SEQ + L0 + r) * 128 + c4 * 4;
        uint2 ua = *(const uint2*)(g_ypart + off);
        uint2 ub = *(const uint2*)(g_ypart + off + (size_t)SEQ*128);
        uint2 uc = *(const uint2*)(g_ypart + off + (size_t)2*SEQ*128);
        float c0 = coef[r], c1 = coef[64 + r], c2 = coef[128 + r];
        float2 a0 = __half22float2(*(const __half2*)&ua.x);
        float2 a1 = __half22float2(*(const __half2*)&ua.y);
        float2 b0 = __half22float2(*(const __half2*)&ub.x);
        float2 b1 = __half22float2(*(const __half2*)&ub.y);
        float2 d0 = __half22float2(*(const __half2*)&uc.x);
        float2 d1 = __half22float2(*(const __half2*)&uc.y);
        float y0 = a0.x*c0 + b0.x*c1 + d0.x*c2, y1 = a0.y*c0 + b0.y*c1 + d0.y*c2;
        float y2 = a1.x*c0 + b1.x*c1 + d1.x*c2, y3 = a1.y*c0 + b1.y*c1 + d1.y*c2;
        *(uint2*)(smc + SM_YF + r * OT_P + c4 * 8) =
            make_uint2(packh2(y0, y1), packh2(y2, y3));
    }
    CP_WAIT(0);
    __syncthreads();

    float acc[8][4];
    #pragma unroll
    for (int j = 0; j < 8; j++)
        #pragma unroll
        for (int q = 0; q < 4; q++) acc[j][q] = 0.f;

    const unsigned aoff0 = (unsigned)(wid * 16 + r8 + (quad & 1) * 8) * OT_P + (unsigned)((quad >> 1) * 16);
    const unsigned boff0 = (unsigned)(r8 + (quad >> 1) * 8) * OT_P + (unsigned)((quad & 1) * 16);

    #pragma unroll
    for (int kk = 0; kk < 8; kk++) {
        unsigned Af[4];
        ldsm4(Af, smb + SM_WZF + aoff0 + kk * 32);
        #pragma unroll
        for (int nb = 0; nb < 4; nb++) {
            unsigned Bf[4];
            ldsm4(Bf, smb + SM_YF + boff0 + (unsigned)(nb * 16) * OT_P + kk * 32);
            mma_f16(acc[2*nb],   Af, Bf);
            mma_f16(acc[2*nb+1], Af, Bf + 2);
        }
    }

    {
        int c0 = C0 + wid * 16 + g;
        int c1 = c0 + 8;
        float b0 = __ldg(bz + c0), b1 = __ldg(bz + c1);
        const float* xr0 = x   + ((size_t)n * 256 + c0) * SEQ + L0;
        const float* xr1 = x   + ((size_t)n * 256 + c1) * SEQ + L0;
        float*       zr0 = out + ((size_t)n * 256 + c0) * SEQ + L0;
        float*       zr1 = out + ((size_t)n * 256 + c1) * SEQ + L0;
        #pragma unroll
        for (int j = 0; j < 8; j++) {
            int l = 8 * j + 2 * t;
            float2 xa = *(const float2*)(xr0 + l);
            float2 xb = *(const float2*)(xr1 + l);
            *(float2*)(zr0 + l) = make_float2(acc[j][0] + b0 + xa.x, acc[j][1] + b0 + xa.y);
            *(float2*)(zr1 + l) = make_float2(acc[j][2] + b1 + xb.x, acc[j][3] + b1 + xb.y);
        }
    }
}

// ---------------------------------------------------------------------------
extern "C" void kernel_launch(void* const* d_in, const int* in_sizes, int n_in,
                              void* d_out, int out_size)
{
    (void)in_sizes; (void)n_in; (void)out_size;
    const float* x  = (const float*)d_in[0];
    const float* gw = (const float*)d_in[1];
    const float* gb = (const float*)d_in[2];
    const float* tw = (const float*)d_in[3];
    const float* tb = (const float*)d_in[4];
    const float* pw = (const float*)d_in[5];
    const float* pb = (const float*)d_in[6];
    const float* zw = (const float*)d_in[7];
    const float* zb = (const float*)d_in[8];
    float* out = (float*)d_out;

    cudaFuncSetAttribute(proj_tc,     cudaFuncAttributeMaxDynamicSharedMemorySize, PROJ_SMEM);
    cudaFuncSetAttribute(attn_kernel, cudaFuncAttributeMaxDynamicSharedMemorySize, ATTN_SMEM);
    cudaFuncSetAttribute(out_tc,      cudaFuncAttributeMaxDynamicSharedMemorySize, OUT_SMEM);

    split_kernel<<<3264, 256>>>(x, gw, tw, pw, zw);
    proj_tc<<<dim3(49, 3, 2),       256, PROJ_SMEM>>>(gb, tb, pb);
    attn_kernel<<<dim3(49, KCH, 2), 256, ATTN_SMEM>>>();
    out_tc<<<dim3(98, 2, 2),        256, OUT_SMEM>>>(x, zb, out);
}

// round 17
// speedup vs baseline: 1.0385x; 1.0205x over previous
#include <cuda_runtime.h>
#include <cuda_bf16.h>
#include <cuda_fp16.h>

#define SEQ    6272
#define KCH    3       // key chunks (split-K)
#define LOG2E  1.44269504f

// ---------------- device scratch (allocation-free) ----------------
__device__ __align__(256) __nv_bfloat16 g_xh[2*256*SEQ], g_xl[2*256*SEQ];   // x split, (n,c,l)
__device__ __align__(256) __nv_bfloat16 g_wsh[3*128*256], g_wsl[3*128*256]; // g,theta,phi weights
__device__ __align__(256) __half       g_wzf[256*128];                       // wz single fp16
__device__ __align__(256) __nv_bfloat16 g_qh[2*SEQ*128], g_ql[2*SEQ*128];   // theta, (n,l,h)
__device__ __align__(256) __nv_bfloat16 g_kh[2*SEQ*128], g_kl[2*SEQ*128];   // phi * log2e, (n,l,h)
__device__ __align__(256) __half       g_vf[2*128*SEQ];                      // g, fp16, (n,h,l)
__device__ __align__(256) __half       g_ypart[2*KCH*SEQ*128];               // normalized partial y (fp16)
__device__ __align__(256) float g_zp[2*KCH*SEQ], g_mp[2*KCH*SEQ];            // partial Z, shift m (log2)

__device__ __forceinline__ unsigned smaddr(const void* p) {
    unsigned r;
    asm("{.reg .u64 t; cvta.to.shared.u64 t, %1; cvt.u32.u64 %0, t;}" : "=r"(r) : "l"(p));
    return r;
}
__device__ __forceinline__ void cp16(unsigned s, const void* g) {
    asm volatile("cp.async.cg.shared.global [%0], [%1], 16;" :: "r"(s), "l"(g) : "memory");
}
#define CP_COMMIT()  asm volatile("cp.async.commit_group;" ::: "memory")
#define CP_WAIT(N)   asm volatile("cp.async.wait_group %0;" :: "n"(N) : "memory")

__device__ __forceinline__ void ldsm4(unsigned* r, unsigned a) {
    asm volatile("ldmatrix.sync.aligned.m8n8.x4.shared.b16 {%0,%1,%2,%3}, [%4];"
        : "=r"(r[0]), "=r"(r[1]), "=r"(r[2]), "=r"(r[3]) : "r"(a));
}
__device__ __forceinline__ void ldsm4t(unsigned* r, unsigned a) {
    asm volatile("ldmatrix.sync.aligned.m8n8.x4.trans.shared.b16 {%0,%1,%2,%3}, [%4];"
        : "=r"(r[0]), "=r"(r[1]), "=r"(r[2]), "=r"(r[3]) : "r"(a));
}
__device__ __forceinline__ void mma_bf16(float* c, const unsigned* a, const unsigned* b) {
    asm volatile("mma.sync.aligned.m16n8k16.row.col.f32.bf16.bf16.f32 "
        "{%0,%1,%2,%3}, {%4,%5,%6,%7}, {%8,%9}, {%0,%1,%2,%3};"
        : "+f"(c[0]), "+f"(c[1]), "+f"(c[2]), "+f"(c[3])
        : "r"(a[0]), "r"(a[1]), "r"(a[2]), "r"(a[3]), "r"(b[0]), "r"(b[1]));
}
__device__ __forceinline__ void mma_f16(float* c, const unsigned* a, const unsigned* b) {
    asm volatile("mma.sync.aligned.m16n8k16.row.col.f32.f16.f16.f32 "
        "{%0,%1,%2,%3}, {%4,%5,%6,%7}, {%8,%9}, {%0,%1,%2,%3};"
        : "+f"(c[0]), "+f"(c[1]), "+f"(c[2]), "+f"(c[3])
        : "r"(a[0]), "r"(a[1]), "r"(a[2]), "r"(a[3]), "r"(b[0]), "r"(b[1]));
}
__device__ __forceinline__ void splitpack(float a, float b, unsigned &h, unsigned &l) {
    __nv_bfloat16 ha = __float2bfloat16(a), hb = __float2bfloat16(b);
    float la = a - __bfloat162float(ha), lb = b - __bfloat162float(hb);
    __nv_bfloat16 lA = __float2bfloat16(la), lB = __float2bfloat16(lb);
    h = (unsigned)__bfloat16_as_ushort(ha) | ((unsigned)__bfloat16_as_ushort(hb) << 16);
    l = (unsigned)__bfloat16_as_ushort(lA) | ((unsigned)__bfloat16_as_ushort(lB) << 16);
}
__device__ __forceinline__ unsigned packh2(float lo, float hi) {
    unsigned u;
    asm("cvt.rn.f16x2.f32 %0, %1, %2;" : "=r"(u) : "f"(hi), "f"(lo));
    return u;
}
__device__ __forceinline__ float ex2(float x) {
    float r;
    asm("ex2.approx.ftz.f32 %0, %1;" : "=f"(r) : "f"(x));
    return r;
}
__device__ __forceinline__ unsigned ex2h2(unsigned x) {
    unsigned r;
    asm("ex2.approx.f16x2 %0, %1;" : "=r"(r) : "r"(x));
    return r;
}

// ---------------------------------------------------------------------------
// Kernel 0: split x + g/theta/phi weights into bf16 hi/lo; wz into fp16.
// ---------------------------------------------------------------------------
__global__ void __launch_bounds__(256) split_kernel(
    const float* __restrict__ x,
    const float* __restrict__ gw, const float* __restrict__ tw,
    const float* __restrict__ pw, const float* __restrict__ zw)
{
    const int bid = blockIdx.x, tid = threadIdx.x;
    if (bid < 3136) {
        int i = bid * 256 + tid;
        float4 v = ((const float4*)x)[i];
        unsigned h0, l0, h1, l1;
        splitpack(v.x, v.y, h0, l0);
        splitpack(v.z, v.w, h1, l1);
        *(uint2*)(g_xh + 4*(size_t)i) = make_uint2(h0, h1);
        *(uint2*)(g_xl + 4*(size_t)i) = make_uint2(l0, l1);
    } else {
        int j = (bid - 3136) * 256 + tid;
        int lj = j & 8191;
        if (j < 24576) {
            const float* src;
            __nv_bfloat16 *dh, *dl;
            if (j < 8192)       { src = gw; dh = g_wsh;           dl = g_wsl; }
            else if (j < 16384) { src = tw; dh = g_wsh + 32768;   dl = g_wsl + 32768; }
            else                { src = pw; dh = g_wsh + 65536;   dl = g_wsl + 65536; }
            float4 v = ((const float4*)src)[lj];
            unsigned h0, l0, h1, l1;
            splitpack(v.x, v.y, h0, l0);
            splitpack(v.z, v.w, h1, l1);
            *(uint2*)(dh + 4*lj) = make_uint2(h0, h1);
            *(uint2*)(dl + 4*lj) = make_uint2(l0, l1);
        } else {
            float4 v = ((const float4*)zw)[lj];
            *(uint2*)(g_wzf + 4*lj) = make_uint2(packh2(v.x, v.y), packh2(v.z, v.w));
        }
    }
}

// ---------------------------------------------------------------------------
// Kernel 1: projections on HMMA (3-pass bf16). Q out: bf16 hi/lo.
// K (pidx 2) out: bf16 hi/lo of (phi * log2e). V (pidx 0) out: fp16, (n,h,l).
// ---------------------------------------------------------------------------
#define PJ_XP 272
#define PJ_WP 144
#define SM_PX 0
#define SM_PW 69632
#define EP_P  272
#define PROJ_SMEM 143360

__global__ void __launch_bounds__(256, 1) proj_tc(
    const float* __restrict__ gb, const float* __restrict__ tb,
    const float* __restrict__ pb)
{
    extern __shared__ char smc[];
    const unsigned smb = smaddr(smc);
    const int tid = threadIdx.x, wid = tid >> 5, lane = tid & 31;
    const int g = lane >> 2, t = lane & 3, r8 = lane & 7, quad = lane >> 3;
    const int pidx = blockIdx.y, nn = blockIdx.z;
    const int L0 = blockIdx.x * 128;
    const int rw = wid * 16;

    const float* bias = (pidx == 0) ? gb : (pidx == 1) ? tb : pb;
    const __nv_bfloat16* Xh = g_xh + (size_t)nn * 256 * SEQ;
    const __nv_bfloat16* Xl = g_xl + (size_t)nn * 256 * SEQ;
    const __nv_bfloat16* Wh = g_wsh + pidx * 32768;
    const __nv_bfloat16* Wl = g_wsl + pidx * 32768;

    auto load_chunk = [&](int ck, int buf) {
        const unsigned xb = smb + SM_PX + buf * 34816;
        const unsigned wb = smb + SM_PW + buf * 36864;
        #pragma unroll
        for (int k = 0; k < 8; k++) {
            int c = tid + 256 * k;
            int half = c >> 10, cc = c & 1023;
            int row = cc >> 4, col8 = cc & 15;
            cp16(xb + half * 17408 + row * PJ_XP + col8 * 16,
                 (half ? Xl : Xh) + ((size_t)(ck * 64 + row)) * SEQ + L0 + col8 * 8);
        }
        #pragma unroll
        for (int k = 0; k < 8; k++) {
            int c = tid + 256 * k;
            int half = c >> 10, cc = c & 1023;
            int row = cc >> 3, col8 = cc & 7;
            cp16(wb + half * 18432 + row * PJ_WP + col8 * 16,
                 (half ? Wl : Wh) + (size_t)row * 256 + ck * 64 + col8 * 8);
        }
        CP_COMMIT();
    };

    load_chunk(0, 0);

    float s[16][4];
    #pragma unroll
    for (int i = 0; i < 16; i++)
        #pragma unroll
        for (int j = 0; j < 4; j++) s[i][j] = 0.f;

    const unsigned xt_rowA = (unsigned)((quad >> 1) * 8 + r8);
    const unsigned xt_colA = (unsigned)(rw + (quad & 1) * 8) * 2;
    const unsigned xt_rowB = (unsigned)((quad & 1) * 8 + r8);
    const unsigned wB_row = (unsigned)(r8 + (quad >> 1) * 8);
    const unsigned wB_col = (unsigned)((quad & 1) * 16);
    const unsigned wA_off0 = (unsigned)(rw + r8 + (quad & 1) * 8) * PJ_WP + (unsigned)((quad >> 1) * 16);

    for (int ck = 0; ck < 4; ck++) {
        const int b = ck & 1;
        if (ck + 1 < 4) { load_chunk(ck + 1, b ^ 1); CP_WAIT(1); }
        else            { CP_WAIT(0); }
        __syncthreads();

        const unsigned xh = smb + SM_PX + b * 34816, xl = xh + 17408;
        const unsigned wh = smb + SM_PW + b * 36864, wl = wh + 18432;

        if (pidx != 0) {
            #pragma unroll
            for (int kk = 0; kk < 4; kk++) {
                unsigned Ah[4], Al[4];
                unsigned aoff = (kk * 16 + xt_rowA) * PJ_XP + xt_colA;
                ldsm4t(Ah, xh + aoff);
                ldsm4t(Al, xl + aoff);
                #pragma unroll
                for (int nb = 0; nb < 8; nb++) {
                    unsigned Bh[4], Bl[4];
                    unsigned boff = (nb * 16 + wB_row) * PJ_WP + kk * 32 + wB_col;
                    ldsm4(Bh, wh + boff);
                    ldsm4(Bl, wl + boff);
                    mma_bf16(s[2*nb],   Ah, Bh);  mma_bf16(s[2*nb+1], Ah, Bh + 2);
                    mma_bf16(s[2*nb],   Ah, Bl);  mma_bf16(s[2*nb+1], Ah, Bl + 2);
                    mma_bf16(s[2*nb],   Al, Bh);  mma_bf16(s[2*nb+1], Al, Bh + 2);
                }
            }
        } else {
            #pragma unroll
            for (int kk = 0; kk < 4; kk++) {
                unsigned Ah[4], Al[4];
                unsigned aoff = wA_off0 + kk * 32;
                ldsm4(Ah, wh + aoff);
                ldsm4(Al, wl + aoff);
                #pragma unroll
                for (int nb = 0; nb < 8; nb++) {
                    unsigned Bh[4], Bl[4];
                    unsigned boff = (kk * 16 + xt_rowB) * PJ_XP + (nb * 16 + (quad >> 1) * 8) * 2;
                    ldsm4t(Bh, xh + boff);
                    ldsm4t(Bl, xl + boff);
                    mma_bf16(s[2*nb],   Ah, Bh);  mma_bf16(s[2*nb+1], Ah, Bh + 2);
                    mma_bf16(s[2*nb],   Ah, Bl);  mma_bf16(s[2*nb+1], Ah, Bl + 2);
                    mma_bf16(s[2*nb],   Al, Bh);  mma_bf16(s[2*nb+1], Al, Bh + 2);
                }
            }
        }
        __syncthreads();
    }

    if (pidx != 0) {
        const float sc = (pidx == 2) ? LOG2E : 1.0f;
        #pragma unroll
        for (int j = 0; j < 16; j++) {
            int h = 8 * j + 2 * t;
            float b0 = __ldg(bias + h), b1 = __ldg(bias + h + 1);
            unsigned hw, lw;
            splitpack((s[j][0] + b0) * sc, (s[j][1] + b1) * sc, hw, lw);
            *(unsigned*)(smc + (rw + g) * EP_P + h * 2)           = hw;
            *(unsigned*)(smc + 34816 + (rw + g) * EP_P + h * 2)   = lw;
            splitpack((s[j][2] + b0) * sc, (s[j][3] + b1) * sc, hw, lw);
            *(unsigned*)(smc + (rw + g + 8) * EP_P + h * 2)         = hw;
            *(unsigned*)(smc + 34816 + (rw + g + 8) * EP_P + h * 2) = lw;
        }
        __syncthreads();
        __nv_bfloat16* Dh = (pidx == 1) ? g_qh : g_kh;
        __nv_bfloat16* Dl = (pidx == 1) ? g_ql : g_kl;
        #pragma unroll
        for (int k = 0; k < 8; k++) {
            int idx = tid + 256 * k;
            int row = idx >> 4, c16 = idx & 15;
            size_t go = ((size_t)nn * SEQ + L0 + row) * 128 + c16 * 8;
            *(uint4*)(Dh + go) = *(const uint4*)(smc + row * EP_P + c16 * 16);
            *(uint4*)(Dl + go) = *(const uint4*)(smc + 34816 + row * EP_P + c16 * 16);
        }
    } else {
        const int h0 = rw + g;
        float br0 = __ldg(bias + h0), br1 = __ldg(bias + h0 + 8);
        #pragma unroll
        for (int j = 0; j < 16; j++) {
            int l = 8 * j + 2 * t;
            *(unsigned*)(smc + h0 * EP_P + l * 2)       = packh2(s[j][0] + br0, s[j][1] + br0);
            *(unsigned*)(smc + (h0 + 8) * EP_P + l * 2) = packh2(s[j][2] + br1, s[j][3] + br1);
        }
        __syncthreads();
        #pragma unroll
        for (int k = 0; k < 8; k++) {
            int idx = tid + 256 * k;
            int row = idx >> 4, c16 = idx & 15;
            size_t go = ((size_t)nn * 128 + row) * SEQ + L0 + c16 * 8;
            *(uint4*)(g_vf + go) = *(const uint4*)(smc + row * EP_P + c16 * 16);
        }
    }
}

// ---------------------------------------------------------------------------
// Kernel 2: flash attention — 128-KEY TILES (halved softmax/sync overhead).
// Q staged through K-buf0 smem, hoisted to registers, then overwritten.
// QK 3-pass bf16 (log2 domain), PV fp16, ex2h2 exponentials.
// 49 tiles of 128 keys split 17/16/16 across KCH chunks.
// ---------------------------------------------------------------------------
#define QSTR 272
#define SM_K  0            // 2 bufs x (hi 34816 + lo 34816) = 139264
#define SM_V  139264       // 2 bufs x 34816 (fp16, 128 keys)
#define ATTN_SMEM 208896

__device__ __forceinline__ void load_kv(
    unsigned smb, int jt, int buf, int tid,
    const __nv_bfloat16* Kh, const __nv_bfloat16* Kl,
    const __half* Vf)
{
    const unsigned kb = smb + SM_K + buf * 69632;
    const unsigned vb = smb + SM_V + buf * 34816;
    #pragma unroll
    for (int k = 0; k < 16; k++) {                // K: 128 rows x 128ch, hi+lo
        int c = tid + 256 * k;
        int half = c >> 11, cc = c & 2047;
        int row = cc >> 4, col16 = cc & 15;
        cp16(kb + half * 34816 + row * QSTR + col16 * 16,
             (half ? Kl : Kh) + ((size_t)(jt * 128 + row)) * 128 + col16 * 8);
    }
    #pragma unroll
    for (int k = 0; k < 8; k++) {                 // V^T fp16: 128 rows(ch) x 128 keys
        int c = tid + 256 * k;
        int row = c >> 4, col = c & 15;
        cp16(vb + row * QSTR + col * 16,
             Vf + (size_t)row * SEQ + jt * 128 + col * 8);
    }
}

__global__ void __launch_bounds__(256, 1) attn_kernel()
{
    extern __shared__ char smc[];
    const unsigned smb = smaddr(smc);
    const int tid = threadIdx.x, wid = tid >> 5, lane = tid & 31;
    const int g = lane >> 2, t = lane & 3, r8 = lane & 7, quad = lane >> 3;
    const int kc = blockIdx.y, n = blockIdx.z, q0 = blockIdx.x * 128;
    const int start = kc * 16 + (kc ? 1 : 0);     // 0 / 17 / 33
    const int cnt = kc ? 16 : 17;
    const int rw = wid * 16;

    const __nv_bfloat16* Qh = g_qh + (size_t)n * SEQ * 128;
    const __nv_bfloat16* Ql = g_ql + (size_t)n * SEQ * 128;
    const __nv_bfloat16* Kh = g_kh + (size_t)n * SEQ * 128;
    const __nv_bfloat16* Kl = g_kl + (size_t)n * SEQ * 128;
    const __half*        Vf = g_vf + (size_t)n * 128 * SEQ;

    const unsigned qa_off = (unsigned)(rw + r8 + (quad & 1) * 8) * QSTR + (unsigned)(quad >> 1) * 16;
    const unsigned kb_off = (unsigned)(r8 + (quad >> 1) * 8) * QSTR + (unsigned)(quad & 1) * 16;
    const unsigned vb_off = (unsigned)(r8 + (quad >> 1) * 8) * QSTR + (unsigned)(quad & 1) * 16;

    // ---- prologue: stage Q in K-buf0 space, hoist to registers, free it ----
    #pragma unroll
    for (int k = 0; k < 16; k++) {
        int c = tid + 256 * k;
        int half = c >> 11, cc = c & 2047;
        int row = cc >> 4, col16 = cc & 15;
        cp16(smb + half * 34816 + row * QSTR + col16 * 16,
             (half ? Ql : Qh) + ((size_t)(q0 + row)) * 128 + col16 * 8);
    }
    CP_COMMIT();
    CP_WAIT(0);
    __syncthreads();

    unsigned Aqh[8][4], Aql[8][4];
    #pragma unroll
    for (int kk = 0; kk < 8; kk++) {
        ldsm4(Aqh[kk], smb + qa_off + kk * 32);
        ldsm4(Aql[kk], smb + 34816 + qa_off + kk * 32);
    }
    __syncthreads();                              // all warps done reading Q

    load_kv(smb, start, 0, tid, Kh, Kl, Vf);
    CP_COMMIT();

    float o[16][4];
    #pragma unroll
    for (int i = 0; i < 16; i++)
        #pragma unroll
        for (int j = 0; j < 4; j++) o[i][j] = 0.f;
    float z0 = 0.f, z1 = 0.f, m0 = -1e30f, m1 = -1e30f;

    for (int it = 0; it < cnt; it++) {
        const int b = it & 1;
        if (it + 1 < cnt) {
            load_kv(smb, start + it + 1, b ^ 1, tid, Kh, Kl, Vf);
            CP_COMMIT();
            CP_WAIT(1);
        } else {
            CP_WAIT(0);
        }
        __syncthreads();

        // ---- S = Q K^T over 128 keys ----
        float s[16][4];
        #pragma unroll
        for (int i = 0; i < 16; i++)
            #pragma unroll
            for (int j = 0; j < 4; j++) s[i][j] = 0.f;

        const unsigned kbh = smb + SM_K + b * 69632;
        const unsigned kbl = kbh + 34816;
        #pragma unroll
        for (int kk = 0; kk < 8; kk++) {
            #pragma unroll
            for (int np = 0; np < 8; np++) {
                unsigned Bh[4], Bl[4];
                unsigned off = kb_off + (unsigned)np * (16 * QSTR) + kk * 32;
                ldsm4(Bh, kbh + off);
                ldsm4(Bl, kbl + off);
                mma_bf16(s[2*np],   Aqh[kk], Bh);   mma_bf16(s[2*np+1], Aqh[kk], Bh + 2);
                mma_bf16(s[2*np],   Aqh[kk], Bl);   mma_bf16(s[2*np+1], Aqh[kk], Bl + 2);
                mma_bf16(s[2*np],   Aql[kk], Bh);   mma_bf16(s[2*np+1], Aql[kk], Bh + 2);
            }
        }

        // ---- online softmax (one pass per 128 keys) ----
        {
            float a0 = -1e30f, a1 = -1e30f;
            #pragma unroll
            for (int i = 0; i < 16; i++) {
                a0 = fmaxf(a0, fmaxf(s[i][0], s[i][1]));
                a1 = fmaxf(a1, fmaxf(s[i][2], s[i][3]));
            }
            a0 = fmaxf(a0, __shfl_xor_sync(0xffffffffu, a0, 1));
            a0 = fmaxf(a0, __shfl_xor_sync(0xffffffffu, a0, 2));
            a1 = fmaxf(a1, __shfl_xor_sync(0xffffffffu, a1, 1));
            a1 = fmaxf(a1, __shfl_xor_sync(0xffffffffu, a1, 2));
            float mn0 = fmaxf(m0, a0), mn1 = fmaxf(m1, a1);
            float al0 = ex2(m0 - mn0), al1 = ex2(m1 - mn1);
            m0 = mn0; m1 = mn1;
            if (!__all_sync(0xffffffffu, (al0 == 1.0f) && (al1 == 1.0f))) {
                z0 *= al0; z1 *= al1;
                #pragma unroll
                for (int ct = 0; ct < 16; ct++) {
                    o[ct][0] *= al0; o[ct][1] *= al0;
                    o[ct][2] *= al1; o[ct][3] *= al1;
                }
            }
        }

        // ---- packed-fp16 exponentials -> PV A fragments ----
        unsigned Pf[32];
        #pragma unroll
        for (int i = 0; i < 16; i++) {
            Pf[2*i]     = ex2h2(packh2(s[i][0] - m0, s[i][1] - m0));
            Pf[2*i + 1] = ex2h2(packh2(s[i][2] - m1, s[i][3] - m1));
            float2 f0 = __half22float2(*(const __half2*)&Pf[2*i]);
            float2 f1 = __half22float2(*(const __half2*)&Pf[2*i + 1]);
            z0 += f0.x + f0.y;
            z1 += f1.x + f1.y;
        }

        // ---- PV: single-pass fp16, K dim = 128 keys ----
        const unsigned vbf = smb + SM_V + b * 34816;
        #pragma unroll
        for (int kk = 0; kk < 8; kk++) {
            #pragma unroll
            for (int cp = 0; cp < 8; cp++) {
                unsigned Bf[4];
                ldsm4(Bf, vbf + vb_off + (unsigned)cp * (16 * QSTR) + kk * 32);
                mma_f16(o[2*cp],   Pf + 4*kk, Bf);
                mma_f16(o[2*cp+1], Pf + 4*kk, Bf + 2);
            }
        }
        __syncthreads();
    }

    z0 += __shfl_xor_sync(0xffffffffu, z0, 1);
    z0 += __shfl_xor_sync(0xffffffffu, z0, 2);
    z1 += __shfl_xor_sync(0xffffffffu, z1, 1);
    z1 += __shfl_xor_sync(0xffffffffu, z1, 2);
    const float i0 = 1.0f / z0, i1 = 1.0f / z1;

    const size_t rbase = ((size_t)(n * KCH + kc)) * SEQ + q0 + rw + g;
    __half* y0 = g_ypart + rbase * 128;
    __half* y1 = y0 + 8 * 128;
    #pragma unroll
    for (int ct = 0; ct < 16; ct++) {
        int col = 8 * ct + 2 * t;
        *(unsigned*)(y0 + col) = packh2(o[ct][0] * i0, o[ct][1] * i0);
        *(unsigned*)(y1 + col) = packh2(o[ct][2] * i1, o[ct][3] * i1);
    }
    if (t == 0) {
        g_zp[rbase]     = z0;  g_mp[rbase]     = m0;
        g_zp[rbase + 8] = z1;  g_mp[rbase + 8] = m1;
    }
}

// ---------------------------------------------------------------------------
// Kernel 3: combine normalized fp16 partials + output projection (fp16 MMA).
// ---------------------------------------------------------------------------
#define OT_P 272
#define SM_WZF 0
#define SM_YF  34816
#define SM_CF  52224
#define OUT_SMEM 52992

__global__ void __launch_bounds__(256, 2) out_tc(
    const float* __restrict__ x, const float* __restrict__ bz,
    float* __restrict__ out)
{
    extern __shared__ char smc[];
    const unsigned smb = smaddr(smc);
    float* coef = (float*)(smc + SM_CF);
    const int tid = threadIdx.x, wid = tid >> 5, lane = tid & 31;
    const int g = lane >> 2, t = lane & 3, r8 = lane & 7, quad = lane >> 3;
    const int ch = blockIdx.y, n = blockIdx.z;
    const int L0 = blockIdx.x * 64;
    const int C0 = ch * 128;

    #pragma unroll
    for (int k = 0; k < 8; k++) {
        int c = tid + 256 * k;
        int row = c >> 4, col8 = c & 15;
        cp16(smb + SM_WZF + row * OT_P + col8 * 16,
             g_wzf + (size_t)(C0 + row) * 128 + col8 * 8);
    }
    CP_COMMIT();

    if (tid < 64) {
        size_t b0 = (size_t)(n * KCH) * SEQ + L0 + tid;
        float m0 = g_mp[b0], m1 = g_mp[b0 + SEQ], m2 = g_mp[b0 + 2*SEQ];
        float M = fmaxf(m0, fmaxf(m1, m2));
        float w0 = ex2(m0 - M) * g_zp[b0];
        float w1 = ex2(m1 - M) * g_zp[b0 + SEQ];
        float w2 = ex2(m2 - M) * g_zp[b0 + 2*SEQ];
        float iZ = 1.0f / (w0 + w1 + w2);
        coef[tid] = w0*iZ; coef[64 + tid] = w1*iZ; coef[128 + tid] = w2*iZ;
    }
    __syncthreads();

    #pragma unroll
    for (int k = 0; k < 8; k++) {
        int idx = tid + 256 * k;
        int r = idx >> 5, c4 = idx & 31;
        size_t off = ((size_t)(n * KCH) * SEQ + L0 + r) * 128 + c4 * 4;
        uint2 ua = *(const uint2*)(g_ypart + off);
        uint2 ub = *(const uint2*)(g_ypart + off + (size_t)SEQ*128);
        uint2 uc = *(const uint2*)(g_ypart + off + (size_t)2*SEQ*128);
        float c0 = coef[r], c1 = coef[64 + r], c2 = coef[128 + r];
        float2 a0 = __half22float2(*(const __half2*)&ua.x);
        float2 a1 = __half22float2(*(const __half2*)&ua.y);
        float2 b0 = __half22float2(*(const __half2*)&ub.x);
        float2 b1 = __half22float2(*(const __half2*)&ub.y);
        float2 d0 = __half22float2(*(const __half2*)&uc.x);
        float2 d1 = __half22float2(*(const __half2*)&uc.y);
        float y0 = a0.x*c0 + b0.x*c1 + d0.x*c2, y1 = a0.y*c0 + b0.y*c1 + d0.y*c2;
        float y2 = a1.x*c0 + b1.x*c1 + d1.x*c2, y3 = a1.y*c0 + b1.y*c1 + d1.y*c2;
        *(uint2*)(smc + SM_YF + r * OT_P + c4 * 8) =
            make_uint2(packh2(y0, y1), packh2(y2, y3));
    }
    CP_WAIT(0);
    __syncthreads();

    float acc[8][4];
    #pragma unroll
    for (int j = 0; j < 8; j++)
        #pragma unroll
        for (int q = 0; q < 4; q++) acc[j][q] = 0.f;

    const unsigned aoff0 = (unsigned)(wid * 16 + r8 + (quad & 1) * 8) * OT_P + (unsigned)((quad >> 1) * 16);
    const unsigned boff0 = (unsigned)(r8 + (quad >> 1) * 8) * OT_P + (unsigned)((quad & 1) * 16);

    #pragma unroll
    for (int kk = 0; kk < 8; kk++) {
        unsigned Af[4];
        ldsm4(Af, smb + SM_WZF + aoff0 + kk * 32);
        #pragma unroll
        for (int nb = 0; nb < 4; nb++) {
            unsigned Bf[4];
            ldsm4(Bf, smb + SM_YF + boff0 + (unsigned)(nb * 16) * OT_P + kk * 32);
            mma_f16(acc[2*nb],   Af, Bf);
            mma_f16(acc[2*nb+1], Af, Bf + 2);
        }
    }

    {
        int c0 = C0 + wid * 16 + g;
        int c1 = c0 + 8;
        float b0 = __ldg(bz + c0), b1 = __ldg(bz + c1);
        const float* xr0 = x   + ((size_t)n * 256 + c0) * SEQ + L0;
        const float* xr1 = x   + ((size_t)n * 256 + c1) * SEQ + L0;
        float*       zr0 = out + ((size_t)n * 256 + c0) * SEQ + L0;
        float*       zr1 = out + ((size_t)n * 256 + c1) * SEQ + L0;
        #pragma unroll
        for (int j = 0; j < 8; j++) {
            int l = 8 * j + 2 * t;
            float2 xa = *(const float2*)(xr0 + l);
            float2 xb = *(const float2*)(xr1 + l);
            *(float2*)(zr0 + l) = make_float2(acc[j][0] + b0 + xa.x, acc[j][1] + b0 + xa.y);
            *(float2*)(zr1 + l) = make_float2(acc[j][2] + b1 + xb.x, acc[j][3] + b1 + xb.y);
        }
    }
}

// ---------------------------------------------------------------------------
extern "C" void kernel_launch(void* const* d_in, const int* in_sizes, int n_in,
                              void* d_out, int out_size)
{
    (void)in_sizes; (void)n_in; (void)out_size;
    const float* x  = (const float*)d_in[0];
    const float* gw = (const float*)d_in[1];
    const float* gb = (const float*)d_in[2];
    const float* tw = (const float*)d_in[3];
    const float* tb = (const float*)d_in[4];
    const float* pw = (const float*)d_in[5];
    const float* pb = (const float*)d_in[6];
    const float* zw = (const float*)d_in[7];
    const float* zb = (const float*)d_in[8];
    float* out = (float*)d_out;

    cudaFuncSetAttribute(proj_tc,     cudaFuncAttributeMaxDynamicSharedMemorySize, PROJ_SMEM);
    cudaFuncSetAttribute(attn_kernel, cudaFuncAttributeMaxDynamicSharedMemorySize, ATTN_SMEM);
    cudaFuncSetAttribute(out_tc,      cudaFuncAttributeMaxDynamicSharedMemorySize, OUT_SMEM);

    split_kernel<<<3264, 256>>>(x, gw, tw, pw, zw);
    proj_tc<<<dim3(49, 3, 2),       256, PROJ_SMEM>>>(gb, tb, pb);
    attn_kernel<<<dim3(49, KCH, 2), 256, ATTN_SMEM>>>();
    out_tc<<<dim3(98, 2, 2),        256, OUT_SMEM>>>(x, zb, out);
}